// round 1
// baseline (speedup 1.0000x reference)
#include <cuda_runtime.h>

#define BS   2
#define SEQ  2048
#define DM   1024
#define NH   16
#define HD   64
#define BH   (BS*NH)
#define SCALEF 64.0f

// Scratch for head-split projected Q/K/V: [b, h, s, hd]
__device__ float g_Qh[BS*NH*SEQ*HD];
__device__ float g_Kh[BS*NH*SEQ*HD];
__device__ float g_Vh[BS*NH*SEQ*HD];

// Branch-free fast exp: exp(x) = 2^(x*log2e), magic-number round + deg-4 poly
// + exponent splice. Valid for x <= ~0 (softmax use); clamps to ~0 below -87.
__device__ __forceinline__ float fast_exp(float x) {
    float t = fmaxf(x * 1.4426950408889634f, -126.0f);
    float z = t + 12582912.0f;            // round-to-nearest int (2^23 magic)
    int   i = __float_as_int(z);
    float n = z - 12582912.0f;            // = round(t), exact
    float f = t - n;                      // in [-0.5, 0.5]
    float p =          9.6181291e-3f;     // Taylor of exp(f*ln2)
    p = fmaf(p, f, 5.5504109e-2f);
    p = fmaf(p, f, 2.4022651e-1f);
    p = fmaf(p, f, 6.9314718e-1f);
    p = fmaf(p, f, 1.0f);
    return __int_as_float(__float_as_int(p) + (i << 23));  // * 2^n
}

// ---------------------------------------------------------------------------
// Projection: Y[b,h,s,hd] = X[b*s, :] @ W^T   (W is [out, in], row-major)
// Tile 128x128, TK=16, 256 threads, 8x8 microtile (split 4+4 for bank-free LDS.128)
// ---------------------------------------------------------------------------
__global__ __launch_bounds__(256) void proj_kernel(
    const float* __restrict__ q, const float* __restrict__ k, const float* __restrict__ v,
    const float* __restrict__ Wq, const float* __restrict__ Wk, const float* __restrict__ Wv)
{
    const float* X; const float* W; float* Y;
    if (blockIdx.z == 0)      { X = q; W = Wq; Y = g_Qh; }
    else if (blockIdx.z == 1) { X = k; W = Wk; Y = g_Kh; }
    else                      { X = v; W = Wv; Y = g_Vh; }

    const int m0 = blockIdx.y * 128;
    const int n0 = blockIdx.x * 128;
    const int tid = threadIdx.x;
    const int tx = tid & 15;   // col group
    const int ty = tid >> 4;   // row group

    __shared__ float As[16][132];   // [k][m], padded (132*4 bytes, 16B aligned)
    __shared__ float Bs[16][132];   // [k][n]

    float acc[8][8];
    #pragma unroll
    for (int i = 0; i < 8; i++)
        #pragma unroll
        for (int j = 0; j < 8; j++) acc[i][j] = 0.0f;

    for (int k0 = 0; k0 < DM; k0 += 16) {
        // Load A tile (128 rows x 16 k) and B tile, transposed into smem.
        #pragma unroll
        for (int it = 0; it < 2; it++) {
            int f  = tid + it * 256;          // 0..511 float4 index
            int r  = f >> 2;                  // row 0..127
            int kq = (f & 3) * 4;             // k sub 0,4,8,12
            float4 av = *(const float4*)(X + (size_t)(m0 + r) * DM + k0 + kq);
            As[kq + 0][r] = av.x; As[kq + 1][r] = av.y;
            As[kq + 2][r] = av.z; As[kq + 3][r] = av.w;
            float4 bv = *(const float4*)(W + (size_t)(n0 + r) * DM + k0 + kq);
            Bs[kq + 0][r] = bv.x; Bs[kq + 1][r] = bv.y;
            Bs[kq + 2][r] = bv.z; Bs[kq + 3][r] = bv.w;
        }
        __syncthreads();

        #pragma unroll
        for (int kk = 0; kk < 16; kk++) {
            float a[8], b[8];
            float4 a0 = *(const float4*)&As[kk][ty * 4];
            float4 a1 = *(const float4*)&As[kk][64 + ty * 4];
            float4 b0 = *(const float4*)&Bs[kk][tx * 4];
            float4 b1 = *(const float4*)&Bs[kk][64 + tx * 4];
            a[0]=a0.x; a[1]=a0.y; a[2]=a0.z; a[3]=a0.w;
            a[4]=a1.x; a[5]=a1.y; a[6]=a1.z; a[7]=a1.w;
            b[0]=b0.x; b[1]=b0.y; b[2]=b0.z; b[3]=b0.w;
            b[4]=b1.x; b[5]=b1.y; b[6]=b1.z; b[7]=b1.w;
            #pragma unroll
            for (int i = 0; i < 8; i++)
                #pragma unroll
                for (int j = 0; j < 8; j++)
                    acc[i][j] = fmaf(a[i], b[j], acc[i][j]);
        }
        __syncthreads();
    }

    // Write out in head-split layout [b, h, s, hd]
    #pragma unroll
    for (int i = 0; i < 8; i++) {
        int m = m0 + ((i < 4) ? (ty * 4 + i) : (64 + ty * 4 + (i - 4)));
        int b  = m >> 11;        // /SEQ
        int s  = m & (SEQ - 1);
        #pragma unroll
        for (int j = 0; j < 8; j++) {
            int n = n0 + ((j < 4) ? (tx * 4 + j) : (64 + tx * 4 + (j - 4)));
            int h = n >> 6;
            int d = n & 63;
            Y[(((size_t)(b * NH + h) * SEQ + s) * HD) + d] = acc[i][j];
        }
    }
}

// ---------------------------------------------------------------------------
// Flash attention, fp32, online softmax. One thread = one query row.
// Block = 128 rows of one (b,h); K-tile = 32 keys.
// K stored transposed (KsT[d][j]) so the dot loop reads broadcast float4s.
// ---------------------------------------------------------------------------
__global__ __launch_bounds__(128) void attn_kernel(float* __restrict__ out)
{
    const int bh  = blockIdx.y;              // 0..31
    const int row = blockIdx.x * 128 + threadIdx.x;
    const int tid = threadIdx.x;

    const float* qptr  = g_Qh + ((size_t)bh * SEQ + row) * HD;
    const float* kbase = g_Kh + (size_t)bh * SEQ * HD;
    const float* vbase = g_Vh + (size_t)bh * SEQ * HD;

    float q[HD];
    #pragma unroll
    for (int d4 = 0; d4 < HD / 4; d4++) {
        float4 t = *(const float4*)(qptr + d4 * 4);
        q[4*d4+0]=t.x; q[4*d4+1]=t.y; q[4*d4+2]=t.z; q[4*d4+3]=t.w;
    }

    float o[HD];
    #pragma unroll
    for (int d = 0; d < HD; d++) o[d] = 0.0f;
    float mrun = -1e30f, lrun = 0.0f;

    __shared__ float KsT[HD][36];     // [d][j], pad->36 keeps 16B align, kills conflicts
    __shared__ float Vs[32][HD];

    for (int kt = 0; kt < SEQ / 32; kt++) {
        const float* kb = kbase + (size_t)kt * 32 * HD;
        const float* vb = vbase + (size_t)kt * 32 * HD;
        #pragma unroll
        for (int it = 0; it < 4; it++) {
            int f  = tid + it * 128;          // 0..511 float4 index
            int j  = f >> 4;                  // key 0..31
            int d4 = (f & 15) * 4;
            float4 kv = *(const float4*)(kb + (size_t)j * HD + d4);
            KsT[d4 + 0][j] = kv.x; KsT[d4 + 1][j] = kv.y;
            KsT[d4 + 2][j] = kv.z; KsT[d4 + 3][j] = kv.w;
            float4 vv = *(const float4*)(vb + (size_t)j * HD + d4);
            *(float4*)&Vs[j][d4] = vv;
        }
        __syncthreads();

        // S = q . K^T for 32 keys
        float s[32];
        #pragma unroll
        for (int j = 0; j < 32; j++) s[j] = 0.0f;
        #pragma unroll
        for (int d = 0; d < HD; d++) {
            float qd = q[d];
            #pragma unroll
            for (int j4 = 0; j4 < 8; j4++) {
                float4 kk = *(const float4*)&KsT[d][j4 * 4];
                s[j4*4+0] = fmaf(qd, kk.x, s[j4*4+0]);
                s[j4*4+1] = fmaf(qd, kk.y, s[j4*4+1]);
                s[j4*4+2] = fmaf(qd, kk.z, s[j4*4+2]);
                s[j4*4+3] = fmaf(qd, kk.w, s[j4*4+3]);
            }
        }

        // online softmax (scores are *SCALEF; near-one-hot, running max is mandatory)
        float mloc = s[0];
        #pragma unroll
        for (int j = 1; j < 32; j++) mloc = fmaxf(mloc, s[j]);
        mloc *= SCALEF;
        float mnew = fmaxf(mrun, mloc);
        float corr = fast_exp(mrun - mnew);
        lrun *= corr;
        #pragma unroll
        for (int d = 0; d < HD; d++) o[d] *= corr;

        #pragma unroll
        for (int j = 0; j < 32; j++) {
            float p = fast_exp(fmaf(s[j], SCALEF, -mnew));
            lrun += p;
            #pragma unroll
            for (int d4 = 0; d4 < HD / 4; d4++) {
                float4 vv = *(const float4*)&Vs[j][d4 * 4];
                o[d4*4+0] = fmaf(p, vv.x, o[d4*4+0]);
                o[d4*4+1] = fmaf(p, vv.y, o[d4*4+1]);
                o[d4*4+2] = fmaf(p, vv.z, o[d4*4+2]);
                o[d4*4+3] = fmaf(p, vv.w, o[d4*4+3]);
            }
        }
        mrun = mnew;
        __syncthreads();
    }

    const float inv = 1.0f / lrun;
    const int b = bh >> 4, h = bh & 15;
    float* optr = out + ((size_t)(b * SEQ + row) * DM) + h * HD;
    #pragma unroll
    for (int d4 = 0; d4 < HD / 4; d4++) {
        float4 t;
        t.x = o[4*d4+0] * inv; t.y = o[4*d4+1] * inv;
        t.z = o[4*d4+2] * inv; t.w = o[4*d4+3] * inv;
        *(float4*)(optr + d4 * 4) = t;
    }
}

extern "C" void kernel_launch(void* const* d_in, const int* in_sizes, int n_in,
                              void* d_out, int out_size)
{
    const float* q  = (const float*)d_in[0];
    const float* k  = (const float*)d_in[1];
    const float* v  = (const float*)d_in[2];
    const float* Wq = (const float*)d_in[3];
    const float* Wk = (const float*)d_in[4];
    const float* Wv = (const float*)d_in[5];
    float* out = (float*)d_out;

    // QKV projections: M=4096 rows, N=1024 cols, 3 matrices via grid.z
    dim3 pgrid(DM / 128, (BS * SEQ) / 128, 3);
    proj_kernel<<<pgrid, 256>>>(q, k, v, Wq, Wk, Wv);

    // Flash attention over heads
    dim3 agrid(SEQ / 128, BH);
    attn_kernel<<<agrid, 128>>>(out);
}

// round 6
// speedup vs baseline: 2.6692x; 2.6692x over previous
#include <cuda_runtime.h>
#include <cuda_bf16.h>
#include <cstdint>

#define BS   2
#define SEQ  2048
#define DM   1024
#define NH   16
#define HD   64
#define BH   (BS*NH)
#define SCALEF 64.0f
#define QT   128            // queries per CTA
#define KT   64             // keys per tile
#define NKT  (SEQ/KT)       // 32

// ---------------- bf16 split scratch (uint4 for 16B alignment) --------------
#define NELEM (BH*SEQ*HD)   // 4,194,304
__device__ uint4 g_Qh4[NELEM/8];
__device__ uint4 g_Qm4[NELEM/8];
__device__ uint4 g_Ql4[NELEM/8];
__device__ uint4 g_Kh4[NELEM/8];
__device__ uint4 g_Km4[NELEM/8];
__device__ uint4 g_Kl4[NELEM/8];
__device__ uint4 g_VTh4[NELEM/8];   // V transposed: [bh][d][s]
__device__ uint4 g_VTl4[NELEM/8];

// ---------------- warp-MMA helpers (family-neutral PTX, sm_80+) -------------
__device__ __forceinline__ uint32_t smem_to_u32(const void* p) {
    uint32_t a;
    asm("{ .reg .u64 t; cvta.to.shared.u64 t, %1; cvt.u32.u64 %0, t; }"
        : "=r"(a) : "l"(p));
    return a;
}
__device__ __forceinline__ void ldsm_x4(uint32_t r[4], uint32_t addr) {
    asm volatile("ldmatrix.sync.aligned.m8n8.x4.shared.b16 {%0,%1,%2,%3}, [%4];"
        : "=r"(r[0]), "=r"(r[1]), "=r"(r[2]), "=r"(r[3]) : "r"(addr));
}
__device__ __forceinline__ void mma_bf16(float c[4], const uint32_t a[4], const uint32_t b[2]) {
    asm volatile("mma.sync.aligned.m16n8k16.row.col.f32.bf16.bf16.f32 "
        "{%0,%1,%2,%3}, {%4,%5,%6,%7}, {%8,%9}, {%0,%1,%2,%3};"
        : "+f"(c[0]), "+f"(c[1]), "+f"(c[2]), "+f"(c[3])
        : "r"(a[0]), "r"(a[1]), "r"(a[2]), "r"(a[3]), "r"(b[0]), "r"(b[1]));
}

// Branch-free fast exp (x <= 0 use).
__device__ __forceinline__ float fast_exp(float x) {
    float t = fmaxf(x * 1.4426950408889634f, -126.0f);
    float z = t + 12582912.0f;
    int   i = __float_as_int(z);
    float n = z - 12582912.0f;
    float f = t - n;
    float p =          9.6181291e-3f;
    p = fmaf(p, f, 5.5504109e-2f);
    p = fmaf(p, f, 2.4022651e-1f);
    p = fmaf(p, f, 6.9314718e-1f);
    p = fmaf(p, f, 1.0f);
    return __int_as_float(__float_as_int(p) + (i << 23));
}

__device__ __forceinline__ void split3(float x, __nv_bfloat16& h, __nv_bfloat16& m, __nv_bfloat16& l) {
    h = __float2bfloat16(x);  float r  = x - __bfloat162float(h);
    m = __float2bfloat16(r);  float r2 = r - __bfloat162float(m);
    l = __float2bfloat16(r2);
}

// ---------------------------------------------------------------------------
// Projection GEMM (fp32 FFMA), epilogue emits bf16 splits.
// Q: pre-scaled by 64, 3-way split, [bh][s][hd].
// K: 3-way split, [bh][s][hd].   V: 2-way split, TRANSPOSED [bh][hd][s].
// ---------------------------------------------------------------------------
__global__ __launch_bounds__(256) void proj_kernel(
    const float* __restrict__ q, const float* __restrict__ k, const float* __restrict__ v,
    const float* __restrict__ Wq, const float* __restrict__ Wk, const float* __restrict__ Wv)
{
    const int z = blockIdx.z;
    const float* X; const float* W;
    if (z == 0)      { X = q; W = Wq; }
    else if (z == 1) { X = k; W = Wk; }
    else             { X = v; W = Wv; }

    const int m0 = blockIdx.y * 128;
    const int n0 = blockIdx.x * 128;
    const int tid = threadIdx.x;
    const int tx = tid & 15;
    const int ty = tid >> 4;

    __shared__ float As[16][132];
    __shared__ float Bs[16][132];

    float acc[8][8];
    #pragma unroll
    for (int i = 0; i < 8; i++)
        #pragma unroll
        for (int j = 0; j < 8; j++) acc[i][j] = 0.0f;

    for (int k0 = 0; k0 < DM; k0 += 16) {
        #pragma unroll
        for (int it = 0; it < 2; it++) {
            int f  = tid + it * 256;
            int r  = f >> 2;
            int kq = (f & 3) * 4;
            float4 av = *(const float4*)(X + (size_t)(m0 + r) * DM + k0 + kq);
            As[kq + 0][r] = av.x; As[kq + 1][r] = av.y;
            As[kq + 2][r] = av.z; As[kq + 3][r] = av.w;
            float4 bv = *(const float4*)(W + (size_t)(n0 + r) * DM + k0 + kq);
            Bs[kq + 0][r] = bv.x; Bs[kq + 1][r] = bv.y;
            Bs[kq + 2][r] = bv.z; Bs[kq + 3][r] = bv.w;
        }
        __syncthreads();

        #pragma unroll
        for (int kk = 0; kk < 16; kk++) {
            float a[8], b[8];
            float4 a0 = *(const float4*)&As[kk][ty * 4];
            float4 a1 = *(const float4*)&As[kk][64 + ty * 4];
            float4 b0 = *(const float4*)&Bs[kk][tx * 4];
            float4 b1 = *(const float4*)&Bs[kk][64 + tx * 4];
            a[0]=a0.x; a[1]=a0.y; a[2]=a0.z; a[3]=a0.w;
            a[4]=a1.x; a[5]=a1.y; a[6]=a1.z; a[7]=a1.w;
            b[0]=b0.x; b[1]=b0.y; b[2]=b0.z; b[3]=b0.w;
            b[4]=b1.x; b[5]=b1.y; b[6]=b1.z; b[7]=b1.w;
            #pragma unroll
            for (int i = 0; i < 8; i++)
                #pragma unroll
                for (int j = 0; j < 8; j++)
                    acc[i][j] = fmaf(a[i], b[j], acc[i][j]);
        }
        __syncthreads();
    }

    __nv_bfloat16* qh = (__nv_bfloat16*)g_Qh4;  __nv_bfloat16* qm = (__nv_bfloat16*)g_Qm4;
    __nv_bfloat16* ql = (__nv_bfloat16*)g_Ql4;
    __nv_bfloat16* kh = (__nv_bfloat16*)g_Kh4;  __nv_bfloat16* km = (__nv_bfloat16*)g_Km4;
    __nv_bfloat16* kl = (__nv_bfloat16*)g_Kl4;
    __nv_bfloat16* vth = (__nv_bfloat16*)g_VTh4; __nv_bfloat16* vtl = (__nv_bfloat16*)g_VTl4;

    #pragma unroll
    for (int i = 0; i < 8; i++) {
        int m = m0 + ((i < 4) ? (ty * 4 + i) : (64 + ty * 4 + (i - 4)));
        int b  = m >> 11;
        int s  = m & (SEQ - 1);
        #pragma unroll
        for (int j = 0; j < 8; j++) {
            int n = n0 + ((j < 4) ? (tx * 4 + j) : (64 + tx * 4 + (j - 4)));
            int h = n >> 6;
            int d = n & 63;
            int bh = b * NH + h;
            float x = acc[i][j];
            __nv_bfloat16 sh, sm2, sl;
            if (z == 0) {
                split3(x * SCALEF, sh, sm2, sl);
                size_t idx = ((size_t)bh * SEQ + s) * HD + d;
                qh[idx] = sh; qm[idx] = sm2; ql[idx] = sl;
            } else if (z == 1) {
                split3(x, sh, sm2, sl);
                size_t idx = ((size_t)bh * SEQ + s) * HD + d;
                kh[idx] = sh; km[idx] = sm2; kl[idx] = sl;
            } else {
                sh = __float2bfloat16(x);
                sl = __float2bfloat16(x - __bfloat162float(sh));
                size_t idx = ((size_t)bh * HD + d) * SEQ + s;
                vth[idx] = sh; vtl[idx] = sl;
            }
        }
    }
}

// ---------------------------------------------------------------------------
// FA2-style attention on mma.sync bf16. CTA = (bh, 128 q-rows); 4 warps x 32 rows.
// QK: 6 split terms (3x3, drop {ml,lm,ll}); PV: 3 terms (2x2, drop ll).
// B operands (K [n][k], VT [n][k], k contiguous) use NON-trans ldmatrix:
// col-major B frag = lane holds 2 consecutive-k at fixed n — exactly non-trans.
// Smem tiles XOR-swizzled in 16B chunks: off = row*128 + ((chunk ^ (row&7))<<4)
// ---------------------------------------------------------------------------
#define QH_OFF  0
#define QM_OFF  16384
#define QL_OFF  32768
#define KH_OFF  49152
#define KM_OFF  57344
#define KL_OFF  65536
#define VTH_OFF 73728
#define VTL_OFF 81920
#define SMEM_DYN 90112

__global__ void __launch_bounds__(128) attn_kernel(float* __restrict__ out)
{
    extern __shared__ char sm[];
    const uint32_t sb = smem_to_u32(sm);
    const int tid = threadIdx.x;
    const int w = tid >> 5, lane = tid & 31;
    const int bh = blockIdx.y;
    const int q0 = blockIdx.x * QT;

    // ---- load Q (3 splits) into swizzled smem; one 128B row per thread ----
    {
        size_t gq = (((size_t)bh * SEQ + q0 + tid) * HD) >> 3;
        #pragma unroll
        for (int c = 0; c < 8; c++) {
            uint32_t off = (uint32_t)(tid * 128 + ((c ^ (tid & 7)) << 4));
            *(uint4*)(sm + QH_OFF + off) = g_Qh4[gq + c];
            *(uint4*)(sm + QM_OFF + off) = g_Qm4[gq + c];
            *(uint4*)(sm + QL_OFF + off) = g_Ql4[gq + c];
        }
    }
    __syncthreads();

    // lane-derived ldmatrix address components
    const int lx    = lane & 7;
    const int a_row = lane & 15;         // + mrow0
    const int a_kh  = lane >> 4;         // k half 0/1
    const int b_mat = lane >> 3;
    const int b_nr  = ((b_mat >> 1) << 3) + (lane & 7);  // n row within 16
    const int b_kh  = b_mat & 1;

    // cache Qh A-frags (invariant across ktiles): [m][kc][4]
    uint32_t qhf[2][4][4];
    #pragma unroll
    for (int m = 0; m < 2; m++) {
        int mrow0 = w * 32 + m * 16;
        #pragma unroll
        for (int kc = 0; kc < 4; kc++) {
            uint32_t addr = sb + QH_OFF + (uint32_t)((mrow0 + a_row) * 128)
                          + (uint32_t)(((2 * kc + a_kh) ^ lx) << 4);
            ldsm_x4(qhf[m][kc], addr);
        }
    }

    float o[2][8][4];
    #pragma unroll
    for (int m = 0; m < 2; m++)
        #pragma unroll
        for (int n = 0; n < 8; n++)
            #pragma unroll
            for (int r = 0; r < 4; r++) o[m][n][r] = 0.0f;

    float mrunA[2] = {-1e30f, -1e30f}, mrunB[2] = {-1e30f, -1e30f};
    float lrunA[2] = {0.0f, 0.0f},     lrunB[2] = {0.0f, 0.0f};

    for (int kt = 0; kt < NKT; kt++) {
        // ---- stage K (3 splits) + VT (2 splits): 64 rows x 128B, 2 thr/row ----
        {
            int r = tid & 63, hf = tid >> 6;
            size_t gk = (((size_t)bh * SEQ + (size_t)kt * KT + r) * HD) >> 3;
            size_t gv = (((size_t)bh * HD + r) * SEQ + (size_t)kt * KT) >> 3;
            #pragma unroll
            for (int cc = 0; cc < 4; cc++) {
                int c = hf * 4 + cc;
                uint32_t off = (uint32_t)(r * 128 + ((c ^ (r & 7)) << 4));
                *(uint4*)(sm + KH_OFF  + off) = g_Kh4[gk + c];
                *(uint4*)(sm + KM_OFF  + off) = g_Km4[gk + c];
                *(uint4*)(sm + KL_OFF  + off) = g_Kl4[gk + c];
                *(uint4*)(sm + VTH_OFF + off) = g_VTh4[gv + c];
                *(uint4*)(sm + VTL_OFF + off) = g_VTl4[gv + c];
            }
        }
        __syncthreads();

        // ---- S = Qsplits . Ksplits^T  (6 terms) ----
        float s[2][8][4];
        #pragma unroll
        for (int m = 0; m < 2; m++)
            #pragma unroll
            for (int n = 0; n < 8; n++)
                #pragma unroll
                for (int r = 0; r < 4; r++) s[m][n][r] = 0.0f;

        #pragma unroll
        for (int kc = 0; kc < 4; kc++) {
            uint32_t qmf[2][4], qlf[2][4];
            #pragma unroll
            for (int m = 0; m < 2; m++) {
                int mrow0 = w * 32 + m * 16;
                uint32_t ab = (uint32_t)((mrow0 + a_row) * 128)
                            + (uint32_t)(((2 * kc + a_kh) ^ lx) << 4);
                ldsm_x4(qmf[m], sb + QM_OFF + ab);
                ldsm_x4(qlf[m], sb + QL_OFF + ab);
            }
            #pragma unroll
            for (int np = 0; np < 4; np++) {
                uint32_t bb = (uint32_t)((np * 16 + b_nr) * 128)
                            + (uint32_t)(((2 * kc + b_kh) ^ lx) << 4);
                uint32_t BH_[4], BM_[4], BL_[4];
                ldsm_x4(BH_, sb + KH_OFF + bb);
                ldsm_x4(BM_, sb + KM_OFF + bb);
                ldsm_x4(BL_, sb + KL_OFF + bb);
                #pragma unroll
                for (int m = 0; m < 2; m++) {
                    #pragma unroll
                    for (int nt = 0; nt < 2; nt++) {
                        float* acc = s[m][2 * np + nt];
                        mma_bf16(acc, qhf[m][kc], BH_ + 2 * nt);
                        mma_bf16(acc, qhf[m][kc], BM_ + 2 * nt);
                        mma_bf16(acc, qmf[m],     BH_ + 2 * nt);
                        mma_bf16(acc, qmf[m],     BM_ + 2 * nt);
                        mma_bf16(acc, qhf[m][kc], BL_ + 2 * nt);
                        mma_bf16(acc, qlf[m],     BH_ + 2 * nt);
                    }
                }
            }
        }

        // ---- online softmax + pack P hi/lo into A-frags ----
        uint32_t ph[2][4][4], pl[2][4][4];
        #pragma unroll
        for (int m = 0; m < 2; m++) {
            float mxA = -1e30f, mxB = -1e30f;
            #pragma unroll
            for (int n = 0; n < 8; n++) {
                mxA = fmaxf(mxA, fmaxf(s[m][n][0], s[m][n][1]));
                mxB = fmaxf(mxB, fmaxf(s[m][n][2], s[m][n][3]));
            }
            mxA = fmaxf(mxA, __shfl_xor_sync(0xffffffffu, mxA, 1));
            mxA = fmaxf(mxA, __shfl_xor_sync(0xffffffffu, mxA, 2));
            mxB = fmaxf(mxB, __shfl_xor_sync(0xffffffffu, mxB, 1));
            mxB = fmaxf(mxB, __shfl_xor_sync(0xffffffffu, mxB, 2));
            float mnA = fmaxf(mrunA[m], mxA);
            float mnB = fmaxf(mrunB[m], mxB);
            float cA = fast_exp(mrunA[m] - mnA);
            float cB = fast_exp(mrunB[m] - mnB);
            float sA = 0.0f, sB = 0.0f;
            #pragma unroll
            for (int n = 0; n < 8; n++) {
                s[m][n][0] = fast_exp(s[m][n][0] - mnA); sA += s[m][n][0];
                s[m][n][1] = fast_exp(s[m][n][1] - mnA); sA += s[m][n][1];
                s[m][n][2] = fast_exp(s[m][n][2] - mnB); sB += s[m][n][2];
                s[m][n][3] = fast_exp(s[m][n][3] - mnB); sB += s[m][n][3];
            }
            sA += __shfl_xor_sync(0xffffffffu, sA, 1);
            sA += __shfl_xor_sync(0xffffffffu, sA, 2);
            sB += __shfl_xor_sync(0xffffffffu, sB, 1);
            sB += __shfl_xor_sync(0xffffffffu, sB, 2);
            lrunA[m] = lrunA[m] * cA + sA;
            lrunB[m] = lrunB[m] * cB + sB;
            mrunA[m] = mnA;  mrunB[m] = mnB;
            #pragma unroll
            for (int n = 0; n < 8; n++) {
                o[m][n][0] *= cA; o[m][n][1] *= cA;
                o[m][n][2] *= cB; o[m][n][3] *= cB;
            }
            // pack: A-frag reg r for k-chunk kc comes from S n-tiles 2kc (r0,r1), 2kc+1 (r2,r3)
            #pragma unroll
            for (int kc = 0; kc < 4; kc++) {
                #pragma unroll
                for (int r = 0; r < 4; r++) {
                    int nsrc = 2 * kc + (r >> 1);
                    int base = (r & 1) * 2;      // 0 -> rows g (c0,c1), 1 -> rows g+8 (c2,c3)
                    float e0 = s[m][nsrc][base + 0];
                    float e1 = s[m][nsrc][base + 1];
                    __nv_bfloat162 hv = __floats2bfloat162_rn(e0, e1);
                    float l0 = e0 - __bfloat162float(hv.x);
                    float l1 = e1 - __bfloat162float(hv.y);
                    __nv_bfloat162 lv = __floats2bfloat162_rn(l0, l1);
                    ph[m][kc][r] = *(uint32_t*)&hv;
                    pl[m][kc][r] = *(uint32_t*)&lv;
                }
            }
        }

        // ---- O += Psplits . VTsplits^T  (3 terms) ----
        #pragma unroll
        for (int kc = 0; kc < 4; kc++) {
            #pragma unroll
            for (int np = 0; np < 4; np++) {
                uint32_t bb = (uint32_t)((np * 16 + b_nr) * 128)
                            + (uint32_t)(((2 * kc + b_kh) ^ lx) << 4);
                uint32_t BH_[4], BL_[4];
                ldsm_x4(BH_, sb + VTH_OFF + bb);
                ldsm_x4(BL_, sb + VTL_OFF + bb);
                #pragma unroll
                for (int m = 0; m < 2; m++) {
                    #pragma unroll
                    for (int nt = 0; nt < 2; nt++) {
                        float* acc = o[m][2 * np + nt];
                        mma_bf16(acc, ph[m][kc], BH_ + 2 * nt);
                        mma_bf16(acc, ph[m][kc], BL_ + 2 * nt);
                        mma_bf16(acc, pl[m][kc], BH_ + 2 * nt);
                    }
                }
            }
        }
        __syncthreads();   // protect K/V smem before next tile's stores
    }

    // ---- epilogue: normalize, write fp32 [b, s, h*64 + d] ----
    const int b = bh >> 4, h = bh & (NH - 1);
    #pragma unroll
    for (int m = 0; m < 2; m++) {
        float invA = 1.0f / lrunA[m];
        float invB = 1.0f / lrunB[m];
        int rA = q0 + w * 32 + m * 16 + (lane >> 2);
        int rB = rA + 8;
        #pragma unroll
        for (int n = 0; n < 8; n++) {
            int col = h * HD + n * 8 + (lane & 3) * 2;
            float2 vA = make_float2(o[m][n][0] * invA, o[m][n][1] * invA);
            float2 vB = make_float2(o[m][n][2] * invB, o[m][n][3] * invB);
            *(float2*)(out + ((size_t)b * SEQ + rA) * DM + col) = vA;
            *(float2*)(out + ((size_t)b * SEQ + rB) * DM + col) = vB;
        }
    }
}

extern "C" void kernel_launch(void* const* d_in, const int* in_sizes, int n_in,
                              void* d_out, int out_size)
{
    const float* q  = (const float*)d_in[0];
    const float* k  = (const float*)d_in[1];
    const float* v  = (const float*)d_in[2];
    const float* Wq = (const float*)d_in[3];
    const float* Wk = (const float*)d_in[4];
    const float* Wv = (const float*)d_in[5];
    float* out = (float*)d_out;

    cudaFuncSetAttribute(attn_kernel, cudaFuncAttributeMaxDynamicSharedMemorySize, SMEM_DYN);

    dim3 pgrid(DM / 128, (BS * SEQ) / 128, 3);
    proj_kernel<<<pgrid, 256>>>(q, k, v, Wq, Wk, Wv);

    dim3 agrid(SEQ / QT, BH);
    attn_kernel<<<agrid, 128, SMEM_DYN>>>(out);
}

// round 7
// speedup vs baseline: 2.7992x; 1.0487x over previous
#include <cuda_runtime.h>
#include <cuda_bf16.h>
#include <cstdint>

#define BS   2
#define SEQ  2048
#define DM   1024
#define NH   16
#define HD   64
#define BH   (BS*NH)
#define SCALEF 64.0f
#define QT   128            // queries per CTA
#define KT   64             // keys per tile
#define NKT  (SEQ/KT)       // 32

// ---------------- bf16 split scratch (uint4 for 16B alignment) --------------
#define NELEM (BH*SEQ*HD)   // 4,194,304
__device__ uint4 g_Qh4[NELEM/8];
__device__ uint4 g_Qm4[NELEM/8];
__device__ uint4 g_Ql4[NELEM/8];
__device__ uint4 g_Kh4[NELEM/8];
__device__ uint4 g_Km4[NELEM/8];
__device__ uint4 g_Kl4[NELEM/8];
__device__ uint4 g_VTh4[NELEM/8];   // V transposed: [bh][d][s]
__device__ uint4 g_VTl4[NELEM/8];

// Split inputs for projection MMA: X = {q,k,v} [3][4096][1024], W [3][1024][1024]
#define NX4 (3*4096*1024/8)
#define NW4 (3*1024*1024/8)
__device__ uint4 g_Xh4[NX4];
__device__ uint4 g_Xm4[NX4];
__device__ uint4 g_Xl4[NX4];
__device__ uint4 g_Wh4[NW4];
__device__ uint4 g_Wm4[NW4];
__device__ uint4 g_Wl4[NW4];

// ---------------- warp-MMA helpers (family-neutral PTX, sm_80+) -------------
__device__ __forceinline__ uint32_t smem_to_u32(const void* p) {
    uint32_t a;
    asm("{ .reg .u64 t; cvta.to.shared.u64 t, %1; cvt.u32.u64 %0, t; }"
        : "=r"(a) : "l"(p));
    return a;
}
__device__ __forceinline__ void ldsm_x4(uint32_t r[4], uint32_t addr) {
    asm volatile("ldmatrix.sync.aligned.m8n8.x4.shared.b16 {%0,%1,%2,%3}, [%4];"
        : "=r"(r[0]), "=r"(r[1]), "=r"(r[2]), "=r"(r[3]) : "r"(addr));
}
__device__ __forceinline__ void mma_bf16(float c[4], const uint32_t a[4], const uint32_t b[2]) {
    asm volatile("mma.sync.aligned.m16n8k16.row.col.f32.bf16.bf16.f32 "
        "{%0,%1,%2,%3}, {%4,%5,%6,%7}, {%8,%9}, {%0,%1,%2,%3};"
        : "+f"(c[0]), "+f"(c[1]), "+f"(c[2]), "+f"(c[3])
        : "r"(a[0]), "r"(a[1]), "r"(a[2]), "r"(a[3]), "r"(b[0]), "r"(b[1]));
}

// Branch-free fast exp (x <= 0 use).
__device__ __forceinline__ float fast_exp(float x) {
    float t = fmaxf(x * 1.4426950408889634f, -126.0f);
    float z = t + 12582912.0f;
    int   i = __float_as_int(z);
    float n = z - 12582912.0f;
    float f = t - n;
    float p =          9.6181291e-3f;
    p = fmaf(p, f, 5.5504109e-2f);
    p = fmaf(p, f, 2.4022651e-1f);
    p = fmaf(p, f, 6.9314718e-1f);
    p = fmaf(p, f, 1.0f);
    return __int_as_float(__float_as_int(p) + (i << 23));
}

__device__ __forceinline__ void split3(float x, __nv_bfloat16& h, __nv_bfloat16& m, __nv_bfloat16& l) {
    h = __float2bfloat16(x);  float r  = x - __bfloat162float(h);
    m = __float2bfloat16(r);  float r2 = r - __bfloat162float(m);
    l = __float2bfloat16(r2);
}

// ---------------------------------------------------------------------------
// Prep: split X (q,k,v) and W (Wq,Wk,Wv) into bf16 h/m/l arrays.
// One float4 (4 elems) per loop step; packed uint2 (4 bf16) stores.
// ---------------------------------------------------------------------------
__global__ __launch_bounds__(256) void prep_kernel(
    const float* __restrict__ q, const float* __restrict__ k, const float* __restrict__ v,
    const float* __restrict__ Wq, const float* __restrict__ Wk, const float* __restrict__ Wv)
{
    const int NXf4 = 3 * 4096 * 1024 / 4;     // float4 count for X
    const int NWf4 = 3 * 1024 * 1024 / 4;
    const int total = NXf4 + NWf4;
    for (int i = blockIdx.x * blockDim.x + threadIdx.x; i < total;
         i += gridDim.x * blockDim.x) {
        const float* src;
        uint2 *dh, *dm, *dl;
        int off;
        if (i < NXf4) {
            int z = i / (4096 * 1024 / 4);
            off   = i % (4096 * 1024 / 4);
            src = (z == 0) ? q : (z == 1) ? k : v;
            dh = (uint2*)g_Xh4 + i; dm = (uint2*)g_Xm4 + i; dl = (uint2*)g_Xl4 + i;
        } else {
            int j = i - NXf4;
            int z = j / (1024 * 1024 / 4);
            off   = j % (1024 * 1024 / 4);
            src = (z == 0) ? Wq : (z == 1) ? Wk : Wv;
            dh = (uint2*)g_Wh4 + j; dm = (uint2*)g_Wm4 + j; dl = (uint2*)g_Wl4 + j;
        }
        float4 x = ((const float4*)src)[off];
        __nv_bfloat16 h[4], m[4], l[4];
        split3(x.x, h[0], m[0], l[0]);
        split3(x.y, h[1], m[1], l[1]);
        split3(x.z, h[2], m[2], l[2]);
        split3(x.w, h[3], m[3], l[3]);
        uint2 ph, pm, pl;
        ((__nv_bfloat16*)&ph)[0]=h[0]; ((__nv_bfloat16*)&ph)[1]=h[1];
        ((__nv_bfloat16*)&ph)[2]=h[2]; ((__nv_bfloat16*)&ph)[3]=h[3];
        ((__nv_bfloat16*)&pm)[0]=m[0]; ((__nv_bfloat16*)&pm)[1]=m[1];
        ((__nv_bfloat16*)&pm)[2]=m[2]; ((__nv_bfloat16*)&pm)[3]=m[3];
        ((__nv_bfloat16*)&pl)[0]=l[0]; ((__nv_bfloat16*)&pl)[1]=l[1];
        ((__nv_bfloat16*)&pl)[2]=l[2]; ((__nv_bfloat16*)&pl)[3]=l[3];
        *dh = ph; *dm = pm; *dl = pl;
    }
}

// ---------------------------------------------------------------------------
// Projection GEMM on HMMA: Y = X @ W^T, 6-term bf16 split {hh,hm,mh,mm,hl,lh}.
// Tile 128x128, K-chunk 64, 256 threads = 8 warps (4 m-groups x 2 n-groups).
// Same frag maps / swizzle as attn (A path == Q, B path == K: non-trans ldsm).
// Epilogue emits attention operand splits (Q x64 3-way, K 3-way, VT 2-way).
// ---------------------------------------------------------------------------
#define XH_OFF  0
#define XM_OFF  16384
#define XL_OFF  32768
#define WH_OFF  49152
#define WM_OFF  65536
#define WL_OFF  81920
#define SMEM_PROJ 98304

__global__ void __launch_bounds__(256) proj_mma_kernel()
{
    extern __shared__ char smp[];
    const uint32_t sb = smem_to_u32(smp);
    const int tid  = threadIdx.x;
    const int w    = tid >> 5, lane = tid & 31;
    const int wm   = w & 3;          // 32-row group
    const int wn   = w >> 2;         // 64-col group
    const int z    = blockIdx.z;
    const int m0   = blockIdx.y * 128;
    const int n0   = blockIdx.x * 128;

    const int lx    = lane & 7;
    const int a_row = lane & 15;
    const int a_kh  = lane >> 4;
    const int b_mat = lane >> 3;
    const int b_nr  = ((b_mat >> 1) << 3) + (lane & 7);
    const int b_kh  = b_mat & 1;

    float c[2][8][4];
    #pragma unroll
    for (int m = 0; m < 2; m++)
        #pragma unroll
        for (int n = 0; n < 8; n++)
            #pragma unroll
            for (int r = 0; r < 4; r++) c[m][n][r] = 0.0f;

    for (int k0 = 0; k0 < DM; k0 += 64) {
        const int kq = k0 >> 3;   // uint4 col offset within 1024-elem row
        #pragma unroll
        for (int it = 0; it < 4; it++) {
            int f = tid + it * 256;          // 0..1023
            int r = f >> 3, ch = f & 7;
            uint32_t off = (uint32_t)(r * 128 + ((ch ^ (r & 7)) << 4));
            size_t gx = (size_t)z * 524288 + (size_t)(m0 + r) * 128 + kq + ch;
            *(uint4*)(smp + XH_OFF + off) = g_Xh4[gx];
            *(uint4*)(smp + XM_OFF + off) = g_Xm4[gx];
            *(uint4*)(smp + XL_OFF + off) = g_Xl4[gx];
            size_t gw = (size_t)z * 131072 + (size_t)(n0 + r) * 128 + kq + ch;
            *(uint4*)(smp + WH_OFF + off) = g_Wh4[gw];
            *(uint4*)(smp + WM_OFF + off) = g_Wm4[gw];
            *(uint4*)(smp + WL_OFF + off) = g_Wl4[gw];
        }
        __syncthreads();

        #pragma unroll
        for (int kc = 0; kc < 4; kc++) {
            uint32_t AH[2][4], AM[2][4], AL[2][4];
            #pragma unroll
            for (int m = 0; m < 2; m++) {
                uint32_t ab = (uint32_t)((wm * 32 + m * 16 + a_row) * 128)
                            + (uint32_t)(((2 * kc + a_kh) ^ lx) << 4);
                ldsm_x4(AH[m], sb + XH_OFF + ab);
                ldsm_x4(AM[m], sb + XM_OFF + ab);
                ldsm_x4(AL[m], sb + XL_OFF + ab);
            }
            #pragma unroll
            for (int np = 0; np < 4; np++) {
                uint32_t bb = (uint32_t)((wn * 64 + np * 16 + b_nr) * 128)
                            + (uint32_t)(((2 * kc + b_kh) ^ lx) << 4);
                uint32_t BH_[4], BM_[4], BL_[4];
                ldsm_x4(BH_, sb + WH_OFF + bb);
                ldsm_x4(BM_, sb + WM_OFF + bb);
                ldsm_x4(BL_, sb + WL_OFF + bb);
                // term-major: 4 independent MMAs between accumulator reuses
                #pragma unroll
                for (int m = 0; m < 2; m++)
                    #pragma unroll
                    for (int nt = 0; nt < 2; nt++)
                        mma_bf16(c[m][2 * np + nt], AH[m], BH_ + 2 * nt);
                #pragma unroll
                for (int m = 0; m < 2; m++)
                    #pragma unroll
                    for (int nt = 0; nt < 2; nt++)
                        mma_bf16(c[m][2 * np + nt], AH[m], BM_ + 2 * nt);
                #pragma unroll
                for (int m = 0; m < 2; m++)
                    #pragma unroll
                    for (int nt = 0; nt < 2; nt++)
                        mma_bf16(c[m][2 * np + nt], AM[m], BH_ + 2 * nt);
                #pragma unroll
                for (int m = 0; m < 2; m++)
                    #pragma unroll
                    for (int nt = 0; nt < 2; nt++)
                        mma_bf16(c[m][2 * np + nt], AM[m], BM_ + 2 * nt);
                #pragma unroll
                for (int m = 0; m < 2; m++)
                    #pragma unroll
                    for (int nt = 0; nt < 2; nt++)
                        mma_bf16(c[m][2 * np + nt], AH[m], BL_ + 2 * nt);
                #pragma unroll
                for (int m = 0; m < 2; m++)
                    #pragma unroll
                    for (int nt = 0; nt < 2; nt++)
                        mma_bf16(c[m][2 * np + nt], AL[m], BH_ + 2 * nt);
            }
        }
        __syncthreads();
    }

    // ---- epilogue: split Y into attention operands ----
    __nv_bfloat16* qh = (__nv_bfloat16*)g_Qh4;  __nv_bfloat16* qm = (__nv_bfloat16*)g_Qm4;
    __nv_bfloat16* ql = (__nv_bfloat16*)g_Ql4;
    __nv_bfloat16* kh = (__nv_bfloat16*)g_Kh4;  __nv_bfloat16* km = (__nv_bfloat16*)g_Km4;
    __nv_bfloat16* kl = (__nv_bfloat16*)g_Kl4;
    __nv_bfloat16* vth = (__nv_bfloat16*)g_VTh4; __nv_bfloat16* vtl = (__nv_bfloat16*)g_VTl4;

    #pragma unroll
    for (int m = 0; m < 2; m++) {
        #pragma unroll
        for (int rr = 0; rr < 2; rr++) {          // rr=0: regs 0,1 (row g); rr=1: regs 2,3 (row g+8)
            int row = m0 + wm * 32 + m * 16 + (lane >> 2) + rr * 8;
            int b   = row >> 11;
            int s   = row & (SEQ - 1);
            #pragma unroll
            for (int n = 0; n < 8; n++) {
                int col = n0 + wn * 64 + n * 8 + (lane & 3) * 2;
                int h   = col >> 6;
                int d   = col & 63;
                int bh  = b * NH + h;
                float e0 = c[m][n][rr * 2 + 0];
                float e1 = c[m][n][rr * 2 + 1];
                if (z == 0) { e0 *= SCALEF; e1 *= SCALEF; }
                if (z != 2) {
                    __nv_bfloat16 h0, mm0, l0, h1, mm1, l1;
                    split3(e0, h0, mm0, l0);
                    split3(e1, h1, mm1, l1);
                    size_t idx = ((size_t)bh * SEQ + s) * HD + d;   // d even -> 4B aligned
                    if (z == 0) {
                        *(__nv_bfloat162*)(qh + idx) = __nv_bfloat162(h0, h1);
                        *(__nv_bfloat162*)(qm + idx) = __nv_bfloat162(mm0, mm1);
                        *(__nv_bfloat162*)(ql + idx) = __nv_bfloat162(l0, l1);
                    } else {
                        *(__nv_bfloat162*)(kh + idx) = __nv_bfloat162(h0, h1);
                        *(__nv_bfloat162*)(km + idx) = __nv_bfloat162(mm0, mm1);
                        *(__nv_bfloat162*)(kl + idx) = __nv_bfloat162(l0, l1);
                    }
                } else {
                    __nv_bfloat16 h0 = __float2bfloat16(e0);
                    __nv_bfloat16 l0 = __float2bfloat16(e0 - __bfloat162float(h0));
                    __nv_bfloat16 h1 = __float2bfloat16(e1);
                    __nv_bfloat16 l1 = __float2bfloat16(e1 - __bfloat162float(h1));
                    size_t idx0 = ((size_t)bh * HD + d) * SEQ + s;
                    size_t idx1 = ((size_t)bh * HD + d + 1) * SEQ + s;
                    vth[idx0] = h0; vtl[idx0] = l0;
                    vth[idx1] = h1; vtl[idx1] = l1;
                }
            }
        }
    }
}

// ---------------------------------------------------------------------------
// FA2-style attention on mma.sync bf16. CTA = (bh, 128 q-rows); 4 warps x 32 rows.
// (byte-identical to R6 passing version)
// ---------------------------------------------------------------------------
#define QH_OFF  0
#define QM_OFF  16384
#define QL_OFF  32768
#define KH_OFF  49152
#define KM_OFF  57344
#define KL_OFF  65536
#define VTH_OFF 73728
#define VTL_OFF 81920
#define SMEM_DYN 90112

__global__ void __launch_bounds__(128) attn_kernel(float* __restrict__ out)
{
    extern __shared__ char sm[];
    const uint32_t sb = smem_to_u32(sm);
    const int tid = threadIdx.x;
    const int w = tid >> 5, lane = tid & 31;
    const int bh = blockIdx.y;
    const int q0 = blockIdx.x * QT;

    // ---- load Q (3 splits) into swizzled smem; one 128B row per thread ----
    {
        size_t gq = (((size_t)bh * SEQ + q0 + tid) * HD) >> 3;
        #pragma unroll
        for (int c = 0; c < 8; c++) {
            uint32_t off = (uint32_t)(tid * 128 + ((c ^ (tid & 7)) << 4));
            *(uint4*)(sm + QH_OFF + off) = g_Qh4[gq + c];
            *(uint4*)(sm + QM_OFF + off) = g_Qm4[gq + c];
            *(uint4*)(sm + QL_OFF + off) = g_Ql4[gq + c];
        }
    }
    __syncthreads();

    const int lx    = lane & 7;
    const int a_row = lane & 15;
    const int a_kh  = lane >> 4;
    const int b_mat = lane >> 3;
    const int b_nr  = ((b_mat >> 1) << 3) + (lane & 7);
    const int b_kh  = b_mat & 1;

    uint32_t qhf[2][4][4];
    #pragma unroll
    for (int m = 0; m < 2; m++) {
        int mrow0 = w * 32 + m * 16;
        #pragma unroll
        for (int kc = 0; kc < 4; kc++) {
            uint32_t addr = sb + QH_OFF + (uint32_t)((mrow0 + a_row) * 128)
                          + (uint32_t)(((2 * kc + a_kh) ^ lx) << 4);
            ldsm_x4(qhf[m][kc], addr);
        }
    }

    float o[2][8][4];
    #pragma unroll
    for (int m = 0; m < 2; m++)
        #pragma unroll
        for (int n = 0; n < 8; n++)
            #pragma unroll
            for (int r = 0; r < 4; r++) o[m][n][r] = 0.0f;

    float mrunA[2] = {-1e30f, -1e30f}, mrunB[2] = {-1e30f, -1e30f};
    float lrunA[2] = {0.0f, 0.0f},     lrunB[2] = {0.0f, 0.0f};

    for (int kt = 0; kt < NKT; kt++) {
        {
            int r = tid & 63, hf = tid >> 6;
            size_t gk = (((size_t)bh * SEQ + (size_t)kt * KT + r) * HD) >> 3;
            size_t gv = (((size_t)bh * HD + r) * SEQ + (size_t)kt * KT) >> 3;
            #pragma unroll
            for (int cc = 0; cc < 4; cc++) {
                int c = hf * 4 + cc;
                uint32_t off = (uint32_t)(r * 128 + ((c ^ (r & 7)) << 4));
                *(uint4*)(sm + KH_OFF  + off) = g_Kh4[gk + c];
                *(uint4*)(sm + KM_OFF  + off) = g_Km4[gk + c];
                *(uint4*)(sm + KL_OFF  + off) = g_Kl4[gk + c];
                *(uint4*)(sm + VTH_OFF + off) = g_VTh4[gv + c];
                *(uint4*)(sm + VTL_OFF + off) = g_VTl4[gv + c];
            }
        }
        __syncthreads();

        float s[2][8][4];
        #pragma unroll
        for (int m = 0; m < 2; m++)
            #pragma unroll
            for (int n = 0; n < 8; n++)
                #pragma unroll
                for (int r = 0; r < 4; r++) s[m][n][r] = 0.0f;

        #pragma unroll
        for (int kc = 0; kc < 4; kc++) {
            uint32_t qmf[2][4], qlf[2][4];
            #pragma unroll
            for (int m = 0; m < 2; m++) {
                int mrow0 = w * 32 + m * 16;
                uint32_t ab = (uint32_t)((mrow0 + a_row) * 128)
                            + (uint32_t)(((2 * kc + a_kh) ^ lx) << 4);
                ldsm_x4(qmf[m], sb + QM_OFF + ab);
                ldsm_x4(qlf[m], sb + QL_OFF + ab);
            }
            #pragma unroll
            for (int np = 0; np < 4; np++) {
                uint32_t bb = (uint32_t)((np * 16 + b_nr) * 128)
                            + (uint32_t)(((2 * kc + b_kh) ^ lx) << 4);
                uint32_t BH_[4], BM_[4], BL_[4];
                ldsm_x4(BH_, sb + KH_OFF + bb);
                ldsm_x4(BM_, sb + KM_OFF + bb);
                ldsm_x4(BL_, sb + KL_OFF + bb);
                #pragma unroll
                for (int m = 0; m < 2; m++) {
                    #pragma unroll
                    for (int nt = 0; nt < 2; nt++) {
                        float* acc = s[m][2 * np + nt];
                        mma_bf16(acc, qhf[m][kc], BH_ + 2 * nt);
                        mma_bf16(acc, qhf[m][kc], BM_ + 2 * nt);
                        mma_bf16(acc, qmf[m],     BH_ + 2 * nt);
                        mma_bf16(acc, qmf[m],     BM_ + 2 * nt);
                        mma_bf16(acc, qhf[m][kc], BL_ + 2 * nt);
                        mma_bf16(acc, qlf[m],     BH_ + 2 * nt);
                    }
                }
            }
        }

        uint32_t ph[2][4][4], pl[2][4][4];
        #pragma unroll
        for (int m = 0; m < 2; m++) {
            float mxA = -1e30f, mxB = -1e30f;
            #pragma unroll
            for (int n = 0; n < 8; n++) {
                mxA = fmaxf(mxA, fmaxf(s[m][n][0], s[m][n][1]));
                mxB = fmaxf(mxB, fmaxf(s[m][n][2], s[m][n][3]));
            }
            mxA = fmaxf(mxA, __shfl_xor_sync(0xffffffffu, mxA, 1));
            mxA = fmaxf(mxA, __shfl_xor_sync(0xffffffffu, mxA, 2));
            mxB = fmaxf(mxB, __shfl_xor_sync(0xffffffffu, mxB, 1));
            mxB = fmaxf(mxB, __shfl_xor_sync(0xffffffffu, mxB, 2));
            float mnA = fmaxf(mrunA[m], mxA);
            float mnB = fmaxf(mrunB[m], mxB);
            float cA = fast_exp(mrunA[m] - mnA);
            float cB = fast_exp(mrunB[m] - mnB);
            float sA = 0.0f, sB = 0.0f;
            #pragma unroll
            for (int n = 0; n < 8; n++) {
                s[m][n][0] = fast_exp(s[m][n][0] - mnA); sA += s[m][n][0];
                s[m][n][1] = fast_exp(s[m][n][1] - mnA); sA += s[m][n][1];
                s[m][n][2] = fast_exp(s[m][n][2] - mnB); sB += s[m][n][2];
                s[m][n][3] = fast_exp(s[m][n][3] - mnB); sB += s[m][n][3];
            }
            sA += __shfl_xor_sync(0xffffffffu, sA, 1);
            sA += __shfl_xor_sync(0xffffffffu, sA, 2);
            sB += __shfl_xor_sync(0xffffffffu, sB, 1);
            sB += __shfl_xor_sync(0xffffffffu, sB, 2);
            lrunA[m] = lrunA[m] * cA + sA;
            lrunB[m] = lrunB[m] * cB + sB;
            mrunA[m] = mnA;  mrunB[m] = mnB;
            #pragma unroll
            for (int n = 0; n < 8; n++) {
                o[m][n][0] *= cA; o[m][n][1] *= cA;
                o[m][n][2] *= cB; o[m][n][3] *= cB;
            }
            #pragma unroll
            for (int kc = 0; kc < 4; kc++) {
                #pragma unroll
                for (int r = 0; r < 4; r++) {
                    int nsrc = 2 * kc + (r >> 1);
                    int base = (r & 1) * 2;
                    float e0 = s[m][nsrc][base + 0];
                    float e1 = s[m][nsrc][base + 1];
                    __nv_bfloat162 hv = __floats2bfloat162_rn(e0, e1);
                    float l0 = e0 - __bfloat162float(hv.x);
                    float l1 = e1 - __bfloat162float(hv.y);
                    __nv_bfloat162 lv = __floats2bfloat162_rn(l0, l1);
                    ph[m][kc][r] = *(uint32_t*)&hv;
                    pl[m][kc][r] = *(uint32_t*)&lv;
                }
            }
        }

        #pragma unroll
        for (int kc = 0; kc < 4; kc++) {
            #pragma unroll
            for (int np = 0; np < 4; np++) {
                uint32_t bb = (uint32_t)((np * 16 + b_nr) * 128)
                            + (uint32_t)(((2 * kc + b_kh) ^ lx) << 4);
                uint32_t BH_[4], BL_[4];
                ldsm_x4(BH_, sb + VTH_OFF + bb);
                ldsm_x4(BL_, sb + VTL_OFF + bb);
                #pragma unroll
                for (int m = 0; m < 2; m++) {
                    #pragma unroll
                    for (int nt = 0; nt < 2; nt++) {
                        float* acc = o[m][2 * np + nt];
                        mma_bf16(acc, ph[m][kc], BH_ + 2 * nt);
                        mma_bf16(acc, ph[m][kc], BL_ + 2 * nt);
                        mma_bf16(acc, pl[m][kc], BH_ + 2 * nt);
                    }
                }
            }
        }
        __syncthreads();
    }

    const int b = bh >> 4, h = bh & (NH - 1);
    #pragma unroll
    for (int m = 0; m < 2; m++) {
        float invA = 1.0f / lrunA[m];
        float invB = 1.0f / lrunB[m];
        int rA = q0 + w * 32 + m * 16 + (lane >> 2);
        int rB = rA + 8;
        #pragma unroll
        for (int n = 0; n < 8; n++) {
            int col = h * HD + n * 8 + (lane & 3) * 2;
            float2 vA = make_float2(o[m][n][0] * invA, o[m][n][1] * invA);
            float2 vB = make_float2(o[m][n][2] * invB, o[m][n][3] * invB);
            *(float2*)(out + ((size_t)b * SEQ + rA) * DM + col) = vA;
            *(float2*)(out + ((size_t)b * SEQ + rB) * DM + col) = vB;
        }
    }
}

extern "C" void kernel_launch(void* const* d_in, const int* in_sizes, int n_in,
                              void* d_out, int out_size)
{
    const float* q  = (const float*)d_in[0];
    const float* k  = (const float*)d_in[1];
    const float* v  = (const float*)d_in[2];
    const float* Wq = (const float*)d_in[3];
    const float* Wk = (const float*)d_in[4];
    const float* Wv = (const float*)d_in[5];
    float* out = (float*)d_out;

    cudaFuncSetAttribute(proj_mma_kernel, cudaFuncAttributeMaxDynamicSharedMemorySize, SMEM_PROJ);
    cudaFuncSetAttribute(attn_kernel, cudaFuncAttributeMaxDynamicSharedMemorySize, SMEM_DYN);

    prep_kernel<<<2048, 256>>>(q, k, v, Wq, Wk, Wv);

    dim3 pgrid(DM / 128, (BS * SEQ) / 128, 3);
    proj_mma_kernel<<<pgrid, 256, SMEM_PROJ>>>();

    dim3 agrid(SEQ / QT, BH);
    attn_kernel<<<agrid, 128, SMEM_DYN>>>(out);
}

// round 9
// speedup vs baseline: 4.2865x; 1.5313x over previous
#include <cuda_runtime.h>
#include <cuda_fp16.h>
#include <cstdint>

#define BS   2
#define SEQ  2048
#define DM   1024
#define NH   16
#define HD   64
#define BH   (BS*NH)
#define SCALEF 64.0f
#define QT   128            // queries per CTA
#define KT   64             // keys per tile
#define NKT  (SEQ/KT)       // 32

// ---------------- fp16 split scratch (uint4 for 16B alignment) --------------
#define NELEM (BH*SEQ*HD)   // 4,194,304
__device__ uint4 g_Qh4[NELEM/8];
__device__ uint4 g_Ql4[NELEM/8];
__device__ uint4 g_Kh4[NELEM/8];
__device__ uint4 g_Kl4[NELEM/8];
__device__ uint4 g_VTh4[NELEM/8];   // V transposed: [bh][d][s]
__device__ uint4 g_VTl4[NELEM/8];

// Split inputs for projection MMA: X = {q,k,v} [3][4096][1024], W [3][1024][1024]
#define NX4 (3*4096*1024/8)
#define NW4 (3*1024*1024/8)
__device__ uint4 g_Xh4[NX4];
__device__ uint4 g_Xl4[NX4];
__device__ uint4 g_Wh4[NW4];
__device__ uint4 g_Wl4[NW4];

// ---------------- warp-MMA helpers (family-neutral PTX, sm_80+) -------------
__device__ __forceinline__ uint32_t smem_to_u32(const void* p) {
    uint32_t a;
    asm("{ .reg .u64 t; cvta.to.shared.u64 t, %1; cvt.u32.u64 %0, t; }"
        : "=r"(a) : "l"(p));
    return a;
}
__device__ __forceinline__ void ldsm_x4(uint32_t r[4], uint32_t addr) {
    asm volatile("ldmatrix.sync.aligned.m8n8.x4.shared.b16 {%0,%1,%2,%3}, [%4];"
        : "=r"(r[0]), "=r"(r[1]), "=r"(r[2]), "=r"(r[3]) : "r"(addr));
}
__device__ __forceinline__ void mma_f16(float c[4], const uint32_t a[4], const uint32_t b[2]) {
    asm volatile("mma.sync.aligned.m16n8k16.row.col.f32.f16.f16.f32 "
        "{%0,%1,%2,%3}, {%4,%5,%6,%7}, {%8,%9}, {%0,%1,%2,%3};"
        : "+f"(c[0]), "+f"(c[1]), "+f"(c[2]), "+f"(c[3])
        : "r"(a[0]), "r"(a[1]), "r"(a[2]), "r"(a[3]), "r"(b[0]), "r"(b[1]));
}

// Branch-free fast exp (x <= 0 use).
__device__ __forceinline__ float fast_exp(float x) {
    float t = fmaxf(x * 1.4426950408889634f, -126.0f);
    float z = t + 12582912.0f;
    int   i = __float_as_int(z);
    float n = z - 12582912.0f;
    float f = t - n;
    float p =          9.6181291e-3f;
    p = fmaf(p, f, 5.5504109e-2f);
    p = fmaf(p, f, 2.4022651e-1f);
    p = fmaf(p, f, 6.9314718e-1f);
    p = fmaf(p, f, 1.0f);
    return __int_as_float(__float_as_int(p) + (i << 23));
}

// fp16 2-way split: x = h + l with ~2^-23 relative residual.
__device__ __forceinline__ void split2(float x, __half& h, __half& l) {
    h = __float2half_rn(x);
    l = __float2half_rn(x - __half2float(h));
}

// ---------------------------------------------------------------------------
// Prep: split X (q,k,v) and W (Wq,Wk,Wv) into fp16 h/l arrays.
// ---------------------------------------------------------------------------
__global__ __launch_bounds__(256) void prep_kernel(
    const float* __restrict__ q, const float* __restrict__ k, const float* __restrict__ v,
    const float* __restrict__ Wq, const float* __restrict__ Wk, const float* __restrict__ Wv)
{
    const int NXf4 = 3 * 4096 * 1024 / 4;     // float4 count for X
    const int NWf4 = 3 * 1024 * 1024 / 4;
    const int total = NXf4 + NWf4;
    for (int i = blockIdx.x * blockDim.x + threadIdx.x; i < total;
         i += gridDim.x * blockDim.x) {
        const float* src;
        uint2 *dh, *dl;
        int off;
        if (i < NXf4) {
            int z = i / (4096 * 1024 / 4);
            off   = i % (4096 * 1024 / 4);
            src = (z == 0) ? q : (z == 1) ? k : v;
            dh = (uint2*)g_Xh4 + i; dl = (uint2*)g_Xl4 + i;
        } else {
            int j = i - NXf4;
            int z = j / (1024 * 1024 / 4);
            off   = j % (1024 * 1024 / 4);
            src = (z == 0) ? Wq : (z == 1) ? Wk : Wv;
            dh = (uint2*)g_Wh4 + j; dl = (uint2*)g_Wl4 + j;
        }
        float4 x = ((const float4*)src)[off];
        __half h[4], l[4];
        split2(x.x, h[0], l[0]);
        split2(x.y, h[1], l[1]);
        split2(x.z, h[2], l[2]);
        split2(x.w, h[3], l[3]);
        uint2 ph, pl;
        ((__half*)&ph)[0]=h[0]; ((__half*)&ph)[1]=h[1];
        ((__half*)&ph)[2]=h[2]; ((__half*)&ph)[3]=h[3];
        ((__half*)&pl)[0]=l[0]; ((__half*)&pl)[1]=l[1];
        ((__half*)&pl)[2]=l[2]; ((__half*)&pl)[3]=l[3];
        *dh = ph; *dl = pl;
    }
}

// ---------------------------------------------------------------------------
// Projection GEMM on HMMA: Y = X @ W^T, 3-term fp16 split {hh,hl,lh}.
// Tile 128x128, K-chunk 64, 256 threads = 8 warps (4 m-groups x 2 n-groups).
// Epilogue emits attention operand fp16 2-way splits (Q x64, K, VT).
// ---------------------------------------------------------------------------
#define XH_OFF  0
#define XL_OFF  16384
#define WH_OFF  32768
#define WL_OFF  49152
#define SMEM_PROJ 65536

__global__ void __launch_bounds__(256) proj_mma_kernel()
{
    extern __shared__ char smp[];
    const uint32_t sb = smem_to_u32(smp);
    const int tid  = threadIdx.x;
    const int w    = tid >> 5, lane = tid & 31;
    const int wm   = w & 3;          // 32-row group
    const int wn   = w >> 2;         // 64-col group
    const int z    = blockIdx.z;
    const int m0   = blockIdx.y * 128;
    const int n0   = blockIdx.x * 128;

    const int lx    = lane & 7;
    const int a_row = lane & 15;
    const int a_kh  = lane >> 4;
    const int b_mat = lane >> 3;
    const int b_nr  = ((b_mat >> 1) << 3) + (lane & 7);
    const int b_kh  = b_mat & 1;

    float c[2][8][4];
    #pragma unroll
    for (int m = 0; m < 2; m++)
        #pragma unroll
        for (int n = 0; n < 8; n++)
            #pragma unroll
            for (int r = 0; r < 4; r++) c[m][n][r] = 0.0f;

    for (int k0 = 0; k0 < DM; k0 += 64) {
        const int kq = k0 >> 3;   // uint4 col offset within 1024-elem row
        #pragma unroll
        for (int it = 0; it < 4; it++) {
            int f = tid + it * 256;          // 0..1023
            int r = f >> 3, ch = f & 7;
            uint32_t off = (uint32_t)(r * 128 + ((ch ^ (r & 7)) << 4));
            size_t gx = (size_t)z * 524288 + (size_t)(m0 + r) * 128 + kq + ch;
            *(uint4*)(smp + XH_OFF + off) = g_Xh4[gx];
            *(uint4*)(smp + XL_OFF + off) = g_Xl4[gx];
            size_t gw = (size_t)z * 131072 + (size_t)(n0 + r) * 128 + kq + ch;
            *(uint4*)(smp + WH_OFF + off) = g_Wh4[gw];
            *(uint4*)(smp + WL_OFF + off) = g_Wl4[gw];
        }
        __syncthreads();

        #pragma unroll
        for (int kc = 0; kc < 4; kc++) {
            uint32_t AH[2][4], AL[2][4];
            #pragma unroll
            for (int m = 0; m < 2; m++) {
                uint32_t ab = (uint32_t)((wm * 32 + m * 16 + a_row) * 128)
                            + (uint32_t)(((2 * kc + a_kh) ^ lx) << 4);
                ldsm_x4(AH[m], sb + XH_OFF + ab);
                ldsm_x4(AL[m], sb + XL_OFF + ab);
            }
            #pragma unroll
            for (int np = 0; np < 4; np++) {
                uint32_t bb = (uint32_t)((wn * 64 + np * 16 + b_nr) * 128)
                            + (uint32_t)(((2 * kc + b_kh) ^ lx) << 4);
                uint32_t BH_[4], BL_[4];
                ldsm_x4(BH_, sb + WH_OFF + bb);
                ldsm_x4(BL_, sb + WL_OFF + bb);
                // term-major: 4 independent accumulators between reuses
                #pragma unroll
                for (int m = 0; m < 2; m++)
                    #pragma unroll
                    for (int nt = 0; nt < 2; nt++)
                        mma_f16(c[m][2 * np + nt], AH[m], BH_ + 2 * nt);
                #pragma unroll
                for (int m = 0; m < 2; m++)
                    #pragma unroll
                    for (int nt = 0; nt < 2; nt++)
                        mma_f16(c[m][2 * np + nt], AH[m], BL_ + 2 * nt);
                #pragma unroll
                for (int m = 0; m < 2; m++)
                    #pragma unroll
                    for (int nt = 0; nt < 2; nt++)
                        mma_f16(c[m][2 * np + nt], AL[m], BH_ + 2 * nt);
            }
        }
        __syncthreads();
    }

    // ---- epilogue: split Y into attention operands ----
    __half* qh = (__half*)g_Qh4;   __half* ql = (__half*)g_Ql4;
    __half* kh = (__half*)g_Kh4;   __half* kl = (__half*)g_Kl4;
    __half* vth = (__half*)g_VTh4; __half* vtl = (__half*)g_VTl4;

    #pragma unroll
    for (int m = 0; m < 2; m++) {
        #pragma unroll
        for (int rr = 0; rr < 2; rr++) {   // rr=0: regs 0,1 (row g); rr=1: regs 2,3 (row g+8)
            int row = m0 + wm * 32 + m * 16 + (lane >> 2) + rr * 8;
            int b   = row >> 11;
            int s   = row & (SEQ - 1);
            #pragma unroll
            for (int n = 0; n < 8; n++) {
                int col = n0 + wn * 64 + n * 8 + (lane & 3) * 2;
                int h   = col >> 6;
                int d   = col & 63;
                int bh  = b * NH + h;
                float e0 = c[m][n][rr * 2 + 0];
                float e1 = c[m][n][rr * 2 + 1];
                if (z == 0) { e0 *= SCALEF; e1 *= SCALEF; }
                __half h0, l0, h1, l1;
                split2(e0, h0, l0);
                split2(e1, h1, l1);
                if (z != 2) {
                    size_t idx = ((size_t)bh * SEQ + s) * HD + d;   // d even -> 4B aligned
                    if (z == 0) {
                        *(__half2*)(qh + idx) = __half2(h0, h1);
                        *(__half2*)(ql + idx) = __half2(l0, l1);
                    } else {
                        *(__half2*)(kh + idx) = __half2(h0, h1);
                        *(__half2*)(kl + idx) = __half2(l0, l1);
                    }
                } else {
                    size_t idx0 = ((size_t)bh * HD + d) * SEQ + s;
                    size_t idx1 = ((size_t)bh * HD + d + 1) * SEQ + s;
                    vth[idx0] = h0; vtl[idx0] = l0;
                    vth[idx1] = h1; vtl[idx1] = l1;
                }
            }
        }
    }
}

// ---------------------------------------------------------------------------
// FA2-style attention on mma.sync fp16. CTA = (bh, 128 q-rows); 4 warps x 32 rows.
// QK: 3 terms {qh.kh, qh.kl, ql.kh}; PV: 3 terms {ph.vh, ph.vl, pl.vh}.
// ---------------------------------------------------------------------------
#define QH_OFF  0
#define QL_OFF  16384
#define KH_OFF  32768
#define KL_OFF  40960
#define VTH_OFF 49152
#define VTL_OFF 57344
#define SMEM_DYN 65536

__global__ void __launch_bounds__(128) attn_kernel(float* __restrict__ out)
{
    extern __shared__ char sm[];
    const uint32_t sb = smem_to_u32(sm);
    const int tid = threadIdx.x;
    const int w = tid >> 5, lane = tid & 31;
    const int bh = blockIdx.y;
    const int q0 = blockIdx.x * QT;

    // ---- load Q (2 splits) into swizzled smem; one 128B row per thread ----
    {
        size_t gq = (((size_t)bh * SEQ + q0 + tid) * HD) >> 3;
        #pragma unroll
        for (int c = 0; c < 8; c++) {
            uint32_t off = (uint32_t)(tid * 128 + ((c ^ (tid & 7)) << 4));
            *(uint4*)(sm + QH_OFF + off) = g_Qh4[gq + c];
            *(uint4*)(sm + QL_OFF + off) = g_Ql4[gq + c];
        }
    }
    __syncthreads();

    const int lx    = lane & 7;
    const int a_row = lane & 15;
    const int a_kh  = lane >> 4;
    const int b_mat = lane >> 3;
    const int b_nr  = ((b_mat >> 1) << 3) + (lane & 7);
    const int b_kh  = b_mat & 1;

    // cache Qh A-frags across ktiles
    uint32_t qhf[2][4][4];
    #pragma unroll
    for (int m = 0; m < 2; m++) {
        int mrow0 = w * 32 + m * 16;
        #pragma unroll
        for (int kc = 0; kc < 4; kc++) {
            uint32_t addr = sb + QH_OFF + (uint32_t)((mrow0 + a_row) * 128)
                          + (uint32_t)(((2 * kc + a_kh) ^ lx) << 4);
            ldsm_x4(qhf[m][kc], addr);
        }
    }

    float o[2][8][4];
    #pragma unroll
    for (int m = 0; m < 2; m++)
        #pragma unroll
        for (int n = 0; n < 8; n++)
            #pragma unroll
            for (int r = 0; r < 4; r++) o[m][n][r] = 0.0f;

    float mrunA[2] = {-1e30f, -1e30f}, mrunB[2] = {-1e30f, -1e30f};
    float lrunA[2] = {0.0f, 0.0f},     lrunB[2] = {0.0f, 0.0f};

    for (int kt = 0; kt < NKT; kt++) {
        // ---- stage K (2 splits) + VT (2 splits): 64 rows x 128B, 2 thr/row ----
        {
            int r = tid & 63, hf = tid >> 6;
            size_t gk = (((size_t)bh * SEQ + (size_t)kt * KT + r) * HD) >> 3;
            size_t gv = (((size_t)bh * HD + r) * SEQ + (size_t)kt * KT) >> 3;
            #pragma unroll
            for (int cc = 0; cc < 4; cc++) {
                int c = hf * 4 + cc;
                uint32_t off = (uint32_t)(r * 128 + ((c ^ (r & 7)) << 4));
                *(uint4*)(sm + KH_OFF  + off) = g_Kh4[gk + c];
                *(uint4*)(sm + KL_OFF  + off) = g_Kl4[gk + c];
                *(uint4*)(sm + VTH_OFF + off) = g_VTh4[gv + c];
                *(uint4*)(sm + VTL_OFF + off) = g_VTl4[gv + c];
            }
        }
        __syncthreads();

        // ---- S = Q . K^T  (3 fp16 split terms) ----
        float s[2][8][4];
        #pragma unroll
        for (int m = 0; m < 2; m++)
            #pragma unroll
            for (int n = 0; n < 8; n++)
                #pragma unroll
                for (int r = 0; r < 4; r++) s[m][n][r] = 0.0f;

        #pragma unroll
        for (int kc = 0; kc < 4; kc++) {
            uint32_t qlf[2][4];
            #pragma unroll
            for (int m = 0; m < 2; m++) {
                int mrow0 = w * 32 + m * 16;
                uint32_t ab = (uint32_t)((mrow0 + a_row) * 128)
                            + (uint32_t)(((2 * kc + a_kh) ^ lx) << 4);
                ldsm_x4(qlf[m], sb + QL_OFF + ab);
            }
            #pragma unroll
            for (int np = 0; np < 4; np++) {
                uint32_t bb = (uint32_t)((np * 16 + b_nr) * 128)
                            + (uint32_t)(((2 * kc + b_kh) ^ lx) << 4);
                uint32_t BH_[4], BL_[4];
                ldsm_x4(BH_, sb + KH_OFF + bb);
                ldsm_x4(BL_, sb + KL_OFF + bb);
                #pragma unroll
                for (int m = 0; m < 2; m++)
                    #pragma unroll
                    for (int nt = 0; nt < 2; nt++)
                        mma_f16(s[m][2 * np + nt], qhf[m][kc], BH_ + 2 * nt);
                #pragma unroll
                for (int m = 0; m < 2; m++)
                    #pragma unroll
                    for (int nt = 0; nt < 2; nt++)
                        mma_f16(s[m][2 * np + nt], qhf[m][kc], BL_ + 2 * nt);
                #pragma unroll
                for (int m = 0; m < 2; m++)
                    #pragma unroll
                    for (int nt = 0; nt < 2; nt++)
                        mma_f16(s[m][2 * np + nt], qlf[m], BH_ + 2 * nt);
            }
        }

        // ---- online softmax + pack P hi/lo fp16 into A-frags ----
        uint32_t ph[2][4][4], pl[2][4][4];
        #pragma unroll
        for (int m = 0; m < 2; m++) {
            float mxA = -1e30f, mxB = -1e30f;
            #pragma unroll
            for (int n = 0; n < 8; n++) {
                mxA = fmaxf(mxA, fmaxf(s[m][n][0], s[m][n][1]));
                mxB = fmaxf(mxB, fmaxf(s[m][n][2], s[m][n][3]));
            }
            mxA = fmaxf(mxA, __shfl_xor_sync(0xffffffffu, mxA, 1));
            mxA = fmaxf(mxA, __shfl_xor_sync(0xffffffffu, mxA, 2));
            mxB = fmaxf(mxB, __shfl_xor_sync(0xffffffffu, mxB, 1));
            mxB = fmaxf(mxB, __shfl_xor_sync(0xffffffffu, mxB, 2));
            float mnA = fmaxf(mrunA[m], mxA);
            float mnB = fmaxf(mrunB[m], mxB);
            float cA = fast_exp(mrunA[m] - mnA);
            float cB = fast_exp(mrunB[m] - mnB);
            float sA = 0.0f, sB = 0.0f;
            #pragma unroll
            for (int n = 0; n < 8; n++) {
                s[m][n][0] = fast_exp(s[m][n][0] - mnA); sA += s[m][n][0];
                s[m][n][1] = fast_exp(s[m][n][1] - mnA); sA += s[m][n][1];
                s[m][n][2] = fast_exp(s[m][n][2] - mnB); sB += s[m][n][2];
                s[m][n][3] = fast_exp(s[m][n][3] - mnB); sB += s[m][n][3];
            }
            sA += __shfl_xor_sync(0xffffffffu, sA, 1);
            sA += __shfl_xor_sync(0xffffffffu, sA, 2);
            sB += __shfl_xor_sync(0xffffffffu, sB, 1);
            sB += __shfl_xor_sync(0xffffffffu, sB, 2);
            lrunA[m] = lrunA[m] * cA + sA;
            lrunB[m] = lrunB[m] * cB + sB;
            mrunA[m] = mnA;  mrunB[m] = mnB;
            #pragma unroll
            for (int n = 0; n < 8; n++) {
                o[m][n][0] *= cA; o[m][n][1] *= cA;
                o[m][n][2] *= cB; o[m][n][3] *= cB;
            }
            // pack: A-frag reg r for k-chunk kc from S n-tiles 2kc (r0,r1), 2kc+1 (r2,r3)
            #pragma unroll
            for (int kc = 0; kc < 4; kc++) {
                #pragma unroll
                for (int r = 0; r < 4; r++) {
                    int nsrc = 2 * kc + (r >> 1);
                    int base = (r & 1) * 2;
                    float e0 = s[m][nsrc][base + 0];
                    float e1 = s[m][nsrc][base + 1];
                    __half2 hv;
                    hv.x = __float2half_rn(e0);
                    hv.y = __float2half_rn(e1);
                    __half2 lv;
                    lv.x = __float2half_rn(e0 - __half2float(hv.x));
                    lv.y = __float2half_rn(e1 - __half2float(hv.y));
                    ph[m][kc][r] = *(uint32_t*)&hv;
                    pl[m][kc][r] = *(uint32_t*)&lv;
                }
            }
        }

        // ---- O += P . VT^T  (3 fp16 split terms) ----
        #pragma unroll
        for (int kc = 0; kc < 4; kc++) {
            #pragma unroll
            for (int np = 0; np < 4; np++) {
                uint32_t bb = (uint32_t)((np * 16 + b_nr) * 128)
                            + (uint32_t)(((2 * kc + b_kh) ^ lx) << 4);
                uint32_t BH_[4], BL_[4];
                ldsm_x4(BH_, sb + VTH_OFF + bb);
                ldsm_x4(BL_, sb + VTL_OFF + bb);
                #pragma unroll
                for (int m = 0; m < 2; m++)
                    #pragma unroll
                    for (int nt = 0; nt < 2; nt++)
                        mma_f16(o[m][2 * np + nt], ph[m][kc], BH_ + 2 * nt);
                #pragma unroll
                for (int m = 0; m < 2; m++)
                    #pragma unroll
                    for (int nt = 0; nt < 2; nt++)
                        mma_f16(o[m][2 * np + nt], ph[m][kc], BL_ + 2 * nt);
                #pragma unroll
                for (int m = 0; m < 2; m++)
                    #pragma unroll
                    for (int nt = 0; nt < 2; nt++)
                        mma_f16(o[m][2 * np + nt], pl[m][kc], BH_ + 2 * nt);
            }
        }
        __syncthreads();   // protect K/V smem before next tile's stores
    }

    // ---- epilogue: normalize, write fp32 [b, s, h*64 + d] ----
    const int b = bh >> 4, h = bh & (NH - 1);
    #pragma unroll
    for (int m = 0; m < 2; m++) {
        float invA = 1.0f / lrunA[m];
        float invB = 1.0f / lrunB[m];
        int rA = q0 + w * 32 + m * 16 + (lane >> 2);
        int rB = rA + 8;
        #pragma unroll
        for (int n = 0; n < 8; n++) {
            int col = h * HD + n * 8 + (lane & 3) * 2;
            float2 vA = make_float2(o[m][n][0] * invA, o[m][n][1] * invA);
            float2 vB = make_float2(o[m][n][2] * invB, o[m][n][3] * invB);
            *(float2*)(out + ((size_t)b * SEQ + rA) * DM + col) = vA;
            *(float2*)(out + ((size_t)b * SEQ + rB) * DM + col) = vB;
        }
    }
}

extern "C" void kernel_launch(void* const* d_in, const int* in_sizes, int n_in,
                              void* d_out, int out_size)
{
    const float* q  = (const float*)d_in[0];
    const float* k  = (const float*)d_in[1];
    const float* v  = (const float*)d_in[2];
    const float* Wq = (const float*)d_in[3];
    const float* Wk = (const float*)d_in[4];
    const float* Wv = (const float*)d_in[5];
    float* out = (float*)d_out;

    cudaFuncSetAttribute(proj_mma_kernel, cudaFuncAttributeMaxDynamicSharedMemorySize, SMEM_PROJ);
    cudaFuncSetAttribute(attn_kernel, cudaFuncAttributeMaxDynamicSharedMemorySize, SMEM_DYN);

    prep_kernel<<<2048, 256>>>(q, k, v, Wq, Wk, Wv);

    dim3 pgrid(DM / 128, (BS * SEQ) / 128, 3);
    proj_mma_kernel<<<pgrid, 256, SMEM_PROJ>>>();

    dim3 agrid(SEQ / QT, BH);
    attn_kernel<<<agrid, 128, SMEM_DYN>>>(out);
}

// round 10
// speedup vs baseline: 4.3526x; 1.0154x over previous
#include <cuda_runtime.h>
#include <cuda_fp16.h>
#include <cstdint>

#define BS   2
#define SEQ  2048
#define DM   1024
#define NH   16
#define HD   64
#define BH   (BS*NH)
// Q pre-scale: 64 * log2(e) -> logits in base-2 units, softmax via ex2.approx
#define QSCALE 92.33248261778578f
#define QT   128            // queries per CTA
#define KT   64             // keys per tile
#define NKT  (SEQ/KT)       // 32

// ---------------- fp16 split scratch (uint4 for 16B alignment) --------------
#define NELEM (BH*SEQ*HD)   // 4,194,304
__device__ uint4 g_Qh4[NELEM/8];
__device__ uint4 g_Ql4[NELEM/8];
__device__ uint4 g_Kh4[NELEM/8];
__device__ uint4 g_Kl4[NELEM/8];
__device__ uint4 g_VTh4[NELEM/8];   // V transposed: [bh][d][s]
__device__ uint4 g_VTl4[NELEM/8];

// Split inputs for projection MMA: X = {q,k,v} [3][4096][1024], W [3][1024][1024]
#define NX4 (3*4096*1024/8)
#define NW4 (3*1024*1024/8)
__device__ uint4 g_Xh4[NX4];
__device__ uint4 g_Xl4[NX4];
__device__ uint4 g_Wh4[NW4];
__device__ uint4 g_Wl4[NW4];

// ---------------- warp-MMA helpers (family-neutral PTX, sm_80+) -------------
__device__ __forceinline__ uint32_t smem_to_u32(const void* p) {
    uint32_t a;
    asm("{ .reg .u64 t; cvta.to.shared.u64 t, %1; cvt.u32.u64 %0, t; }"
        : "=r"(a) : "l"(p));
    return a;
}
__device__ __forceinline__ void ldsm_x4(uint32_t r[4], uint32_t addr) {
    asm volatile("ldmatrix.sync.aligned.m8n8.x4.shared.b16 {%0,%1,%2,%3}, [%4];"
        : "=r"(r[0]), "=r"(r[1]), "=r"(r[2]), "=r"(r[3]) : "r"(addr));
}
__device__ __forceinline__ void mma_f16(float c[4], const uint32_t a[4], const uint32_t b[2]) {
    asm volatile("mma.sync.aligned.m16n8k16.row.col.f32.f16.f16.f32 "
        "{%0,%1,%2,%3}, {%4,%5,%6,%7}, {%8,%9}, {%0,%1,%2,%3};"
        : "+f"(c[0]), "+f"(c[1]), "+f"(c[2]), "+f"(c[3])
        : "r"(a[0]), "r"(a[1]), "r"(a[2]), "r"(a[3]), "r"(b[0]), "r"(b[1]));
}

// 2^x on the MUFU pipe (1 instruction vs ~11 FFMA polynomial).
__device__ __forceinline__ float ex2f(float x) {
    float y;
    asm("ex2.approx.f32 %0, %1;" : "=f"(y) : "f"(x));
    return y;
}

// fp16 2-way split: x = h + l with ~2^-23 relative residual.
__device__ __forceinline__ void split2(float x, __half& h, __half& l) {
    h = __float2half_rn(x);
    l = __float2half_rn(x - __half2float(h));
}

// ---------------------------------------------------------------------------
// Prep: split X (q,k,v) and W (Wq,Wk,Wv) into fp16 h/l arrays.
// ---------------------------------------------------------------------------
__global__ __launch_bounds__(256) void prep_kernel(
    const float* __restrict__ q, const float* __restrict__ k, const float* __restrict__ v,
    const float* __restrict__ Wq, const float* __restrict__ Wk, const float* __restrict__ Wv)
{
    const int NXf4 = 3 * 4096 * 1024 / 4;     // float4 count for X
    const int NWf4 = 3 * 1024 * 1024 / 4;
    const int total = NXf4 + NWf4;
    for (int i = blockIdx.x * blockDim.x + threadIdx.x; i < total;
         i += gridDim.x * blockDim.x) {
        const float* src;
        uint2 *dh, *dl;
        int off;
        if (i < NXf4) {
            int z = i / (4096 * 1024 / 4);
            off   = i % (4096 * 1024 / 4);
            src = (z == 0) ? q : (z == 1) ? k : v;
            dh = (uint2*)g_Xh4 + i; dl = (uint2*)g_Xl4 + i;
        } else {
            int j = i - NXf4;
            int z = j / (1024 * 1024 / 4);
            off   = j % (1024 * 1024 / 4);
            src = (z == 0) ? Wq : (z == 1) ? Wk : Wv;
            dh = (uint2*)g_Wh4 + j; dl = (uint2*)g_Wl4 + j;
        }
        float4 x = ((const float4*)src)[off];
        __half h[4], l[4];
        split2(x.x, h[0], l[0]);
        split2(x.y, h[1], l[1]);
        split2(x.z, h[2], l[2]);
        split2(x.w, h[3], l[3]);
        uint2 ph, pl;
        ((__half*)&ph)[0]=h[0]; ((__half*)&ph)[1]=h[1];
        ((__half*)&ph)[2]=h[2]; ((__half*)&ph)[3]=h[3];
        ((__half*)&pl)[0]=l[0]; ((__half*)&pl)[1]=l[1];
        ((__half*)&pl)[2]=l[2]; ((__half*)&pl)[3]=l[3];
        *dh = ph; *dl = pl;
    }
}

// ---------------------------------------------------------------------------
// Projection GEMM on HMMA: Y = X @ W^T, 3-term fp16 split {hh,hl,lh}.
// Tile 128x128, K-chunk 64, 256 threads = 8 warps (4 m-groups x 2 n-groups).
// Epilogue emits attention operand fp16 2-way splits (Q x 64*log2e, K, VT).
// ---------------------------------------------------------------------------
#define XH_OFF  0
#define XL_OFF  16384
#define WH_OFF  32768
#define WL_OFF  49152
#define SMEM_PROJ 65536

__global__ void __launch_bounds__(256) proj_mma_kernel()
{
    extern __shared__ char smp[];
    const uint32_t sb = smem_to_u32(smp);
    const int tid  = threadIdx.x;
    const int w    = tid >> 5, lane = tid & 31;
    const int wm   = w & 3;          // 32-row group
    const int wn   = w >> 2;         // 64-col group
    const int z    = blockIdx.z;
    const int m0   = blockIdx.y * 128;
    const int n0   = blockIdx.x * 128;

    const int lx    = lane & 7;
    const int a_row = lane & 15;
    const int a_kh  = lane >> 4;
    const int b_mat = lane >> 3;
    const int b_nr  = ((b_mat >> 1) << 3) + (lane & 7);
    const int b_kh  = b_mat & 1;

    float c[2][8][4];
    #pragma unroll
    for (int m = 0; m < 2; m++)
        #pragma unroll
        for (int n = 0; n < 8; n++)
            #pragma unroll
            for (int r = 0; r < 4; r++) c[m][n][r] = 0.0f;

    for (int k0 = 0; k0 < DM; k0 += 64) {
        const int kq = k0 >> 3;   // uint4 col offset within 1024-elem row
        #pragma unroll
        for (int it = 0; it < 4; it++) {
            int f = tid + it * 256;          // 0..1023
            int r = f >> 3, ch = f & 7;
            uint32_t off = (uint32_t)(r * 128 + ((ch ^ (r & 7)) << 4));
            size_t gx = (size_t)z * 524288 + (size_t)(m0 + r) * 128 + kq + ch;
            *(uint4*)(smp + XH_OFF + off) = g_Xh4[gx];
            *(uint4*)(smp + XL_OFF + off) = g_Xl4[gx];
            size_t gw = (size_t)z * 131072 + (size_t)(n0 + r) * 128 + kq + ch;
            *(uint4*)(smp + WH_OFF + off) = g_Wh4[gw];
            *(uint4*)(smp + WL_OFF + off) = g_Wl4[gw];
        }
        __syncthreads();

        #pragma unroll
        for (int kc = 0; kc < 4; kc++) {
            uint32_t AH[2][4], AL[2][4];
            #pragma unroll
            for (int m = 0; m < 2; m++) {
                uint32_t ab = (uint32_t)((wm * 32 + m * 16 + a_row) * 128)
                            + (uint32_t)(((2 * kc + a_kh) ^ lx) << 4);
                ldsm_x4(AH[m], sb + XH_OFF + ab);
                ldsm_x4(AL[m], sb + XL_OFF + ab);
            }
            #pragma unroll
            for (int np = 0; np < 4; np++) {
                uint32_t bb = (uint32_t)((wn * 64 + np * 16 + b_nr) * 128)
                            + (uint32_t)(((2 * kc + b_kh) ^ lx) << 4);
                uint32_t BH_[4], BL_[4];
                ldsm_x4(BH_, sb + WH_OFF + bb);
                ldsm_x4(BL_, sb + WL_OFF + bb);
                #pragma unroll
                for (int m = 0; m < 2; m++)
                    #pragma unroll
                    for (int nt = 0; nt < 2; nt++)
                        mma_f16(c[m][2 * np + nt], AH[m], BH_ + 2 * nt);
                #pragma unroll
                for (int m = 0; m < 2; m++)
                    #pragma unroll
                    for (int nt = 0; nt < 2; nt++)
                        mma_f16(c[m][2 * np + nt], AH[m], BL_ + 2 * nt);
                #pragma unroll
                for (int m = 0; m < 2; m++)
                    #pragma unroll
                    for (int nt = 0; nt < 2; nt++)
                        mma_f16(c[m][2 * np + nt], AL[m], BH_ + 2 * nt);
            }
        }
        __syncthreads();
    }

    // ---- epilogue: split Y into attention operands ----
    __half* qh = (__half*)g_Qh4;   __half* ql = (__half*)g_Ql4;
    __half* kh = (__half*)g_Kh4;   __half* kl = (__half*)g_Kl4;
    __half* vth = (__half*)g_VTh4; __half* vtl = (__half*)g_VTl4;

    #pragma unroll
    for (int m = 0; m < 2; m++) {
        #pragma unroll
        for (int rr = 0; rr < 2; rr++) {   // rr=0: regs 0,1 (row g); rr=1: regs 2,3 (row g+8)
            int row = m0 + wm * 32 + m * 16 + (lane >> 2) + rr * 8;
            int b   = row >> 11;
            int s   = row & (SEQ - 1);
            #pragma unroll
            for (int n = 0; n < 8; n++) {
                int col = n0 + wn * 64 + n * 8 + (lane & 3) * 2;
                int h   = col >> 6;
                int d   = col & 63;
                int bh  = b * NH + h;
                float e0 = c[m][n][rr * 2 + 0];
                float e1 = c[m][n][rr * 2 + 1];
                if (z == 0) { e0 *= QSCALE; e1 *= QSCALE; }
                __half h0, l0, h1, l1;
                split2(e0, h0, l0);
                split2(e1, h1, l1);
                if (z != 2) {
                    size_t idx = ((size_t)bh * SEQ + s) * HD + d;   // d even -> 4B aligned
                    if (z == 0) {
                        *(__half2*)(qh + idx) = __half2(h0, h1);
                        *(__half2*)(ql + idx) = __half2(l0, l1);
                    } else {
                        *(__half2*)(kh + idx) = __half2(h0, h1);
                        *(__half2*)(kl + idx) = __half2(l0, l1);
                    }
                } else {
                    size_t idx0 = ((size_t)bh * HD + d) * SEQ + s;
                    size_t idx1 = ((size_t)bh * HD + d + 1) * SEQ + s;
                    vth[idx0] = h0; vtl[idx0] = l0;
                    vth[idx1] = h1; vtl[idx1] = l1;
                }
            }
        }
    }
}

// ---------------------------------------------------------------------------
// FA2-style attention on mma.sync fp16. CTA = (bh, 128 q-rows); 4 warps x 32 rows.
// Logits arrive in base-2 units (Q pre-scaled by 64*log2e): softmax = ex2.
// QK: 3 terms {qh.kh, qh.kl, ql.kh}; PV: 3 terms {ph.vh, ph.vl, pl.vh}.
// ---------------------------------------------------------------------------
#define QH_OFF  0
#define QL_OFF  16384
#define KH_OFF  32768
#define KL_OFF  40960
#define VTH_OFF 49152
#define VTL_OFF 57344
#define SMEM_DYN 65536

__global__ void __launch_bounds__(128) attn_kernel(float* __restrict__ out)
{
    extern __shared__ char sm[];
    const uint32_t sb = smem_to_u32(sm);
    const int tid = threadIdx.x;
    const int w = tid >> 5, lane = tid & 31;
    const int bh = blockIdx.y;
    const int q0 = blockIdx.x * QT;

    // ---- load Q (2 splits) into swizzled smem; one 128B row per thread ----
    {
        size_t gq = (((size_t)bh * SEQ + q0 + tid) * HD) >> 3;
        #pragma unroll
        for (int c = 0; c < 8; c++) {
            uint32_t off = (uint32_t)(tid * 128 + ((c ^ (tid & 7)) << 4));
            *(uint4*)(sm + QH_OFF + off) = g_Qh4[gq + c];
            *(uint4*)(sm + QL_OFF + off) = g_Ql4[gq + c];
        }
    }
    __syncthreads();

    const int lx    = lane & 7;
    const int a_row = lane & 15;
    const int a_kh  = lane >> 4;
    const int b_mat = lane >> 3;
    const int b_nr  = ((b_mat >> 1) << 3) + (lane & 7);
    const int b_kh  = b_mat & 1;

    // cache Qh A-frags across ktiles
    uint32_t qhf[2][4][4];
    #pragma unroll
    for (int m = 0; m < 2; m++) {
        int mrow0 = w * 32 + m * 16;
        #pragma unroll
        for (int kc = 0; kc < 4; kc++) {
            uint32_t addr = sb + QH_OFF + (uint32_t)((mrow0 + a_row) * 128)
                          + (uint32_t)(((2 * kc + a_kh) ^ lx) << 4);
            ldsm_x4(qhf[m][kc], addr);
        }
    }

    float o[2][8][4];
    #pragma unroll
    for (int m = 0; m < 2; m++)
        #pragma unroll
        for (int n = 0; n < 8; n++)
            #pragma unroll
            for (int r = 0; r < 4; r++) o[m][n][r] = 0.0f;

    float mrunA[2] = {-1e30f, -1e30f}, mrunB[2] = {-1e30f, -1e30f};
    float lrunA[2] = {0.0f, 0.0f},     lrunB[2] = {0.0f, 0.0f};

    for (int kt = 0; kt < NKT; kt++) {
        // ---- stage K (2 splits) + VT (2 splits): 64 rows x 128B, 2 thr/row ----
        {
            int r = tid & 63, hf = tid >> 6;
            size_t gk = (((size_t)bh * SEQ + (size_t)kt * KT + r) * HD) >> 3;
            size_t gv = (((size_t)bh * HD + r) * SEQ + (size_t)kt * KT) >> 3;
            #pragma unroll
            for (int cc = 0; cc < 4; cc++) {
                int c = hf * 4 + cc;
                uint32_t off = (uint32_t)(r * 128 + ((c ^ (r & 7)) << 4));
                *(uint4*)(sm + KH_OFF  + off) = g_Kh4[gk + c];
                *(uint4*)(sm + KL_OFF  + off) = g_Kl4[gk + c];
                *(uint4*)(sm + VTH_OFF + off) = g_VTh4[gv + c];
                *(uint4*)(sm + VTL_OFF + off) = g_VTl4[gv + c];
            }
        }
        __syncthreads();

        // ---- S = Q . K^T  (3 fp16 split terms), base-2 logit units ----
        float s[2][8][4];
        #pragma unroll
        for (int m = 0; m < 2; m++)
            #pragma unroll
            for (int n = 0; n < 8; n++)
                #pragma unroll
                for (int r = 0; r < 4; r++) s[m][n][r] = 0.0f;

        #pragma unroll
        for (int kc = 0; kc < 4; kc++) {
            uint32_t qlf[2][4];
            #pragma unroll
            for (int m = 0; m < 2; m++) {
                int mrow0 = w * 32 + m * 16;
                uint32_t ab = (uint32_t)((mrow0 + a_row) * 128)
                            + (uint32_t)(((2 * kc + a_kh) ^ lx) << 4);
                ldsm_x4(qlf[m], sb + QL_OFF + ab);
            }
            #pragma unroll
            for (int np = 0; np < 4; np++) {
                uint32_t bb = (uint32_t)((np * 16 + b_nr) * 128)
                            + (uint32_t)(((2 * kc + b_kh) ^ lx) << 4);
                uint32_t BH_[4], BL_[4];
                ldsm_x4(BH_, sb + KH_OFF + bb);
                ldsm_x4(BL_, sb + KL_OFF + bb);
                #pragma unroll
                for (int m = 0; m < 2; m++)
                    #pragma unroll
                    for (int nt = 0; nt < 2; nt++)
                        mma_f16(s[m][2 * np + nt], qhf[m][kc], BH_ + 2 * nt);
                #pragma unroll
                for (int m = 0; m < 2; m++)
                    #pragma unroll
                    for (int nt = 0; nt < 2; nt++)
                        mma_f16(s[m][2 * np + nt], qhf[m][kc], BL_ + 2 * nt);
                #pragma unroll
                for (int m = 0; m < 2; m++)
                    #pragma unroll
                    for (int nt = 0; nt < 2; nt++)
                        mma_f16(s[m][2 * np + nt], qlf[m], BH_ + 2 * nt);
            }
        }

        // ---- online softmax (base-2, MUFU ex2) + pack P hi/lo fp16 ----
        uint32_t ph[2][4][4], pl[2][4][4];
        #pragma unroll
        for (int m = 0; m < 2; m++) {
            float mxA = -1e30f, mxB = -1e30f;
            #pragma unroll
            for (int n = 0; n < 8; n++) {
                mxA = fmaxf(mxA, fmaxf(s[m][n][0], s[m][n][1]));
                mxB = fmaxf(mxB, fmaxf(s[m][n][2], s[m][n][3]));
            }
            mxA = fmaxf(mxA, __shfl_xor_sync(0xffffffffu, mxA, 1));
            mxA = fmaxf(mxA, __shfl_xor_sync(0xffffffffu, mxA, 2));
            mxB = fmaxf(mxB, __shfl_xor_sync(0xffffffffu, mxB, 1));
            mxB = fmaxf(mxB, __shfl_xor_sync(0xffffffffu, mxB, 2));
            float mnA = fmaxf(mrunA[m], mxA);
            float mnB = fmaxf(mrunB[m], mxB);
            float cA = ex2f(mrunA[m] - mnA);
            float cB = ex2f(mrunB[m] - mnB);
            float sA = 0.0f, sB = 0.0f;
            #pragma unroll
            for (int n = 0; n < 8; n++) {
                s[m][n][0] = ex2f(s[m][n][0] - mnA); sA += s[m][n][0];
                s[m][n][1] = ex2f(s[m][n][1] - mnA); sA += s[m][n][1];
                s[m][n][2] = ex2f(s[m][n][2] - mnB); sB += s[m][n][2];
                s[m][n][3] = ex2f(s[m][n][3] - mnB); sB += s[m][n][3];
            }
            sA += __shfl_xor_sync(0xffffffffu, sA, 1);
            sA += __shfl_xor_sync(0xffffffffu, sA, 2);
            sB += __shfl_xor_sync(0xffffffffu, sB, 1);
            sB += __shfl_xor_sync(0xffffffffu, sB, 2);
            lrunA[m] = lrunA[m] * cA + sA;
            lrunB[m] = lrunB[m] * cB + sB;
            mrunA[m] = mnA;  mrunB[m] = mnB;
            #pragma unroll
            for (int n = 0; n < 8; n++) {
                o[m][n][0] *= cA; o[m][n][1] *= cA;
                o[m][n][2] *= cB; o[m][n][3] *= cB;
            }
            // pack: A-frag reg r for k-chunk kc from S n-tiles 2kc (r0,r1), 2kc+1 (r2,r3)
            #pragma unroll
            for (int kc = 0; kc < 4; kc++) {
                #pragma unroll
                for (int r = 0; r < 4; r++) {
                    int nsrc = 2 * kc + (r >> 1);
                    int base = (r & 1) * 2;
                    float e0 = s[m][nsrc][base + 0];
                    float e1 = s[m][nsrc][base + 1];
                    __half2 hv = __floats2half2_rn(e0, e1);
                    float2 hf2 = __half22float2(hv);
                    __half2 lv = __floats2half2_rn(e0 - hf2.x, e1 - hf2.y);
                    ph[m][kc][r] = *(uint32_t*)&hv;
                    pl[m][kc][r] = *(uint32_t*)&lv;
                }
            }
        }

        // ---- O += P . VT^T  (3 fp16 split terms) ----
        #pragma unroll
        for (int kc = 0; kc < 4; kc++) {
            #pragma unroll
            for (int np = 0; np < 4; np++) {
                uint32_t bb = (uint32_t)((np * 16 + b_nr) * 128)
                            + (uint32_t)(((2 * kc + b_kh) ^ lx) << 4);
                uint32_t BH_[4], BL_[4];
                ldsm_x4(BH_, sb + VTH_OFF + bb);
                ldsm_x4(BL_, sb + VTL_OFF + bb);
                #pragma unroll
                for (int m = 0; m < 2; m++)
                    #pragma unroll
                    for (int nt = 0; nt < 2; nt++)
                        mma_f16(o[m][2 * np + nt], ph[m][kc], BH_ + 2 * nt);
                #pragma unroll
                for (int m = 0; m < 2; m++)
                    #pragma unroll
                    for (int nt = 0; nt < 2; nt++)
                        mma_f16(o[m][2 * np + nt], ph[m][kc], BL_ + 2 * nt);
                #pragma unroll
                for (int m = 0; m < 2; m++)
                    #pragma unroll
                    for (int nt = 0; nt < 2; nt++)
                        mma_f16(o[m][2 * np + nt], pl[m][kc], BH_ + 2 * nt);
            }
        }
        __syncthreads();   // protect K/V smem before next tile's stores
    }

    // ---- epilogue: normalize, write fp32 [b, s, h*64 + d] ----
    const int b = bh >> 4, h = bh & (NH - 1);
    #pragma unroll
    for (int m = 0; m < 2; m++) {
        float invA = 1.0f / lrunA[m];
        float invB = 1.0f / lrunB[m];
        int rA = q0 + w * 32 + m * 16 + (lane >> 2);
        int rB = rA + 8;
        #pragma unroll
        for (int n = 0; n < 8; n++) {
            int col = h * HD + n * 8 + (lane & 3) * 2;
            float2 vA = make_float2(o[m][n][0] * invA, o[m][n][1] * invA);
            float2 vB = make_float2(o[m][n][2] * invB, o[m][n][3] * invB);
            *(float2*)(out + ((size_t)b * SEQ + rA) * DM + col) = vA;
            *(float2*)(out + ((size_t)b * SEQ + rB) * DM + col) = vB;
        }
    }
}

extern "C" void kernel_launch(void* const* d_in, const int* in_sizes, int n_in,
                              void* d_out, int out_size)
{
    const float* q  = (const float*)d_in[0];
    const float* k  = (const float*)d_in[1];
    const float* v  = (const float*)d_in[2];
    const float* Wq = (const float*)d_in[3];
    const float* Wk = (const float*)d_in[4];
    const float* Wv = (const float*)d_in[5];
    float* out = (float*)d_out;

    cudaFuncSetAttribute(proj_mma_kernel, cudaFuncAttributeMaxDynamicSharedMemorySize, SMEM_PROJ);
    cudaFuncSetAttribute(attn_kernel, cudaFuncAttributeMaxDynamicSharedMemorySize, SMEM_DYN);

    prep_kernel<<<2048, 256>>>(q, k, v, Wq, Wk, Wv);

    dim3 pgrid(DM / 128, (BS * SEQ) / 128, 3);
    proj_mma_kernel<<<pgrid, 256, SMEM_PROJ>>>();

    dim3 agrid(SEQ / QT, BH);
    attn_kernel<<<agrid, 128, SMEM_DYN>>>(out);
}

// round 11
// speedup vs baseline: 4.5047x; 1.0350x over previous
#include <cuda_runtime.h>
#include <cuda_fp16.h>
#include <cstdint>

#define BS   2
#define SEQ  2048
#define DM   1024
#define NH   16
#define HD   64
#define BH   (BS*NH)
// Q pre-scale: 64 * log2(e) -> logits in base-2 units, softmax via ex2.approx
#define QSCALE 92.33248261778578f
#define QT   128            // queries per CTA
#define KT   64             // keys per tile
#define NKT  (SEQ/KT)       // 32

// ---------------- fp16 split scratch (uint4 for 16B alignment) --------------
#define NELEM (BH*SEQ*HD)   // 4,194,304
__device__ uint4 g_Qh4[NELEM/8];
__device__ uint4 g_Ql4[NELEM/8];
__device__ uint4 g_Kh4[NELEM/8];
__device__ uint4 g_Kl4[NELEM/8];
__device__ uint4 g_VTh4[NELEM/8];   // V transposed: [bh][d][s]
__device__ uint4 g_VTl4[NELEM/8];

// Split inputs for projection MMA: X = {q,k,v} [3][4096][1024], W [3][1024][1024]
#define NX4 (3*4096*1024/8)
#define NW4 (3*1024*1024/8)
__device__ uint4 g_Xh4[NX4];
__device__ uint4 g_Xl4[NX4];
__device__ uint4 g_Wh4[NW4];
__device__ uint4 g_Wl4[NW4];

// ---------------- warp-MMA helpers (family-neutral PTX, sm_80+) -------------
__device__ __forceinline__ uint32_t smem_to_u32(const void* p) {
    uint32_t a;
    asm("{ .reg .u64 t; cvta.to.shared.u64 t, %1; cvt.u32.u64 %0, t; }"
        : "=r"(a) : "l"(p));
    return a;
}
__device__ __forceinline__ void ldsm_x4(uint32_t r[4], uint32_t addr) {
    asm volatile("ldmatrix.sync.aligned.m8n8.x4.shared.b16 {%0,%1,%2,%3}, [%4];"
        : "=r"(r[0]), "=r"(r[1]), "=r"(r[2]), "=r"(r[3]) : "r"(addr));
}
__device__ __forceinline__ void mma_f16(float c[4], const uint32_t a[4], const uint32_t b[2]) {
    asm volatile("mma.sync.aligned.m16n8k16.row.col.f32.f16.f16.f32 "
        "{%0,%1,%2,%3}, {%4,%5,%6,%7}, {%8,%9}, {%0,%1,%2,%3};"
        : "+f"(c[0]), "+f"(c[1]), "+f"(c[2]), "+f"(c[3])
        : "r"(a[0]), "r"(a[1]), "r"(a[2]), "r"(a[3]), "r"(b[0]), "r"(b[1]));
}
// async 16B global->shared copy (bypasses registers)
__device__ __forceinline__ void cp_async16(uint32_t smem_addr, const void* gptr) {
    asm volatile("cp.async.cg.shared.global [%0], [%1], 16;"
        :: "r"(smem_addr), "l"(__cvta_generic_to_global(gptr)) : "memory");
}
#define CP_COMMIT() asm volatile("cp.async.commit_group;" ::: "memory")
#define CP_WAIT(n)  asm volatile("cp.async.wait_group %0;" :: "n"(n) : "memory")

// 2^x on the MUFU pipe.
__device__ __forceinline__ float ex2f(float x) {
    float y;
    asm("ex2.approx.f32 %0, %1;" : "=f"(y) : "f"(x));
    return y;
}

// fp16 2-way split: x = h + l with ~2^-23 relative residual.
__device__ __forceinline__ void split2(float x, __half& h, __half& l) {
    h = __float2half_rn(x);
    l = __float2half_rn(x - __half2float(h));
}

// ---------------------------------------------------------------------------
// Prep: split X (q,k,v) and W (Wq,Wk,Wv) into fp16 h/l arrays.
// ---------------------------------------------------------------------------
__global__ __launch_bounds__(256) void prep_kernel(
    const float* __restrict__ q, const float* __restrict__ k, const float* __restrict__ v,
    const float* __restrict__ Wq, const float* __restrict__ Wk, const float* __restrict__ Wv)
{
    const int NXf4 = 3 * 4096 * 1024 / 4;     // float4 count for X
    const int NWf4 = 3 * 1024 * 1024 / 4;
    const int total = NXf4 + NWf4;
    for (int i = blockIdx.x * blockDim.x + threadIdx.x; i < total;
         i += gridDim.x * blockDim.x) {
        const float* src;
        uint2 *dh, *dl;
        int off;
        if (i < NXf4) {
            int z = i / (4096 * 1024 / 4);
            off   = i % (4096 * 1024 / 4);
            src = (z == 0) ? q : (z == 1) ? k : v;
            dh = (uint2*)g_Xh4 + i; dl = (uint2*)g_Xl4 + i;
        } else {
            int j = i - NXf4;
            int z = j / (1024 * 1024 / 4);
            off   = j % (1024 * 1024 / 4);
            src = (z == 0) ? Wq : (z == 1) ? Wk : Wv;
            dh = (uint2*)g_Wh4 + j; dl = (uint2*)g_Wl4 + j;
        }
        float4 x = ((const float4*)src)[off];
        __half h[4], l[4];
        split2(x.x, h[0], l[0]);
        split2(x.y, h[1], l[1]);
        split2(x.z, h[2], l[2]);
        split2(x.w, h[3], l[3]);
        uint2 ph, pl;
        ((__half*)&ph)[0]=h[0]; ((__half*)&ph)[1]=h[1];
        ((__half*)&ph)[2]=h[2]; ((__half*)&ph)[3]=h[3];
        ((__half*)&pl)[0]=l[0]; ((__half*)&pl)[1]=l[1];
        ((__half*)&pl)[2]=l[2]; ((__half*)&pl)[3]=l[3];
        *dh = ph; *dl = pl;
    }
}

// ---------------------------------------------------------------------------
// Projection GEMM on HMMA: Y = X @ W^T, 3-term fp16 split {hh,hl,lh}.
// (unchanged from R10 passing version)
// ---------------------------------------------------------------------------
#define XH_OFF  0
#define XL_OFF  16384
#define WH_OFF  32768
#define WL_OFF  49152
#define SMEM_PROJ 65536

__global__ void __launch_bounds__(256) proj_mma_kernel()
{
    extern __shared__ char smp[];
    const uint32_t sb = smem_to_u32(smp);
    const int tid  = threadIdx.x;
    const int w    = tid >> 5, lane = tid & 31;
    const int wm   = w & 3;          // 32-row group
    const int wn   = w >> 2;         // 64-col group
    const int z    = blockIdx.z;
    const int m0   = blockIdx.y * 128;
    const int n0   = blockIdx.x * 128;

    const int lx    = lane & 7;
    const int a_row = lane & 15;
    const int a_kh  = lane >> 4;
    const int b_mat = lane >> 3;
    const int b_nr  = ((b_mat >> 1) << 3) + (lane & 7);
    const int b_kh  = b_mat & 1;

    float c[2][8][4];
    #pragma unroll
    for (int m = 0; m < 2; m++)
        #pragma unroll
        for (int n = 0; n < 8; n++)
            #pragma unroll
            for (int r = 0; r < 4; r++) c[m][n][r] = 0.0f;

    for (int k0 = 0; k0 < DM; k0 += 64) {
        const int kq = k0 >> 3;
        #pragma unroll
        for (int it = 0; it < 4; it++) {
            int f = tid + it * 256;
            int r = f >> 3, ch = f & 7;
            uint32_t off = (uint32_t)(r * 128 + ((ch ^ (r & 7)) << 4));
            size_t gx = (size_t)z * 524288 + (size_t)(m0 + r) * 128 + kq + ch;
            *(uint4*)(smp + XH_OFF + off) = g_Xh4[gx];
            *(uint4*)(smp + XL_OFF + off) = g_Xl4[gx];
            size_t gw = (size_t)z * 131072 + (size_t)(n0 + r) * 128 + kq + ch;
            *(uint4*)(smp + WH_OFF + off) = g_Wh4[gw];
            *(uint4*)(smp + WL_OFF + off) = g_Wl4[gw];
        }
        __syncthreads();

        #pragma unroll
        for (int kc = 0; kc < 4; kc++) {
            uint32_t AH[2][4], AL[2][4];
            #pragma unroll
            for (int m = 0; m < 2; m++) {
                uint32_t ab = (uint32_t)((wm * 32 + m * 16 + a_row) * 128)
                            + (uint32_t)(((2 * kc + a_kh) ^ lx) << 4);
                ldsm_x4(AH[m], sb + XH_OFF + ab);
                ldsm_x4(AL[m], sb + XL_OFF + ab);
            }
            #pragma unroll
            for (int np = 0; np < 4; np++) {
                uint32_t bb = (uint32_t)((wn * 64 + np * 16 + b_nr) * 128)
                            + (uint32_t)(((2 * kc + b_kh) ^ lx) << 4);
                uint32_t BH_[4], BL_[4];
                ldsm_x4(BH_, sb + WH_OFF + bb);
                ldsm_x4(BL_, sb + WL_OFF + bb);
                #pragma unroll
                for (int m = 0; m < 2; m++)
                    #pragma unroll
                    for (int nt = 0; nt < 2; nt++)
                        mma_f16(c[m][2 * np + nt], AH[m], BH_ + 2 * nt);
                #pragma unroll
                for (int m = 0; m < 2; m++)
                    #pragma unroll
                    for (int nt = 0; nt < 2; nt++)
                        mma_f16(c[m][2 * np + nt], AH[m], BL_ + 2 * nt);
                #pragma unroll
                for (int m = 0; m < 2; m++)
                    #pragma unroll
                    for (int nt = 0; nt < 2; nt++)
                        mma_f16(c[m][2 * np + nt], AL[m], BH_ + 2 * nt);
            }
        }
        __syncthreads();
    }

    // ---- epilogue: split Y into attention operands ----
    __half* qh = (__half*)g_Qh4;   __half* ql = (__half*)g_Ql4;
    __half* kh = (__half*)g_Kh4;   __half* kl = (__half*)g_Kl4;
    __half* vth = (__half*)g_VTh4; __half* vtl = (__half*)g_VTl4;

    #pragma unroll
    for (int m = 0; m < 2; m++) {
        #pragma unroll
        for (int rr = 0; rr < 2; rr++) {
            int row = m0 + wm * 32 + m * 16 + (lane >> 2) + rr * 8;
            int b   = row >> 11;
            int s   = row & (SEQ - 1);
            #pragma unroll
            for (int n = 0; n < 8; n++) {
                int col = n0 + wn * 64 + n * 8 + (lane & 3) * 2;
                int h   = col >> 6;
                int d   = col & 63;
                int bh  = b * NH + h;
                float e0 = c[m][n][rr * 2 + 0];
                float e1 = c[m][n][rr * 2 + 1];
                if (z == 0) { e0 *= QSCALE; e1 *= QSCALE; }
                __half h0, l0, h1, l1;
                split2(e0, h0, l0);
                split2(e1, h1, l1);
                if (z != 2) {
                    size_t idx = ((size_t)bh * SEQ + s) * HD + d;
                    if (z == 0) {
                        *(__half2*)(qh + idx) = __half2(h0, h1);
                        *(__half2*)(ql + idx) = __half2(l0, l1);
                    } else {
                        *(__half2*)(kh + idx) = __half2(h0, h1);
                        *(__half2*)(kl + idx) = __half2(l0, l1);
                    }
                } else {
                    size_t idx0 = ((size_t)bh * HD + d) * SEQ + s;
                    size_t idx1 = ((size_t)bh * HD + d + 1) * SEQ + s;
                    vth[idx0] = h0; vtl[idx0] = l0;
                    vth[idx1] = h1; vtl[idx1] = l1;
                }
            }
        }
    }
}

// ---------------------------------------------------------------------------
// FA2-style attention, fp16 mma.sync. CTA = (bh, 128 q-rows); 4 warps x 32 rows.
// cp.async DOUBLE-BUFFERED K/V staging; P-repack fused into PV per k-chunk
// (ph/pl transient: -24 live regs for better ptxas scheduling).
// ---------------------------------------------------------------------------
#define QH_OFF   0
#define QL_OFF   16384
#define KV_OFF   32768
#define STAGE_SZ 32768
#define KH_S     0
#define KL_S     8192
#define VTH_S    16384
#define VTL_S    24576
#define SMEM_DYN 98304

__global__ void __launch_bounds__(128) attn_kernel(float* __restrict__ out)
{
    extern __shared__ char sm[];
    const uint32_t sb = smem_to_u32(sm);
    const int tid = threadIdx.x;
    const int w = tid >> 5, lane = tid & 31;
    const int bh = blockIdx.y;
    const int q0 = blockIdx.x * QT;

    // ---- load Q (2 splits) into swizzled smem; one 128B row per thread ----
    {
        size_t gq = (((size_t)bh * SEQ + q0 + tid) * HD) >> 3;
        #pragma unroll
        for (int c = 0; c < 8; c++) {
            uint32_t off = (uint32_t)(tid * 128 + ((c ^ (tid & 7)) << 4));
            *(uint4*)(sm + QH_OFF + off) = g_Qh4[gq + c];
            *(uint4*)(sm + QL_OFF + off) = g_Ql4[gq + c];
        }
    }

    const int lx    = lane & 7;
    const int a_row = lane & 15;
    const int a_kh  = lane >> 4;
    const int b_mat = lane >> 3;
    const int b_nr  = ((b_mat >> 1) << 3) + (lane & 7);
    const int b_kh  = b_mat & 1;

    const int st_r  = tid & 63, st_hf = tid >> 6;   // staging map: 2 thr/row
    const size_t gk_base = ((size_t)bh * SEQ) * HD >> 3;
    const size_t gv_base = ((size_t)bh * HD * SEQ) >> 3;

    // stage kt into buffer p (async, no registers)
    auto stage = [&](int kt, int p) {
        size_t gk = gk_base + ((size_t)kt * KT + st_r) * (HD / 8);
        size_t gv = gv_base + (size_t)st_r * (SEQ / 8) + (size_t)kt * (KT / 8);
        uint32_t base = sb + KV_OFF + p * STAGE_SZ;
        #pragma unroll
        for (int cc = 0; cc < 4; cc++) {
            int c = st_hf * 4 + cc;
            uint32_t off = (uint32_t)(st_r * 128 + ((c ^ (st_r & 7)) << 4));
            cp_async16(base + KH_S  + off, g_Kh4  + gk + c);
            cp_async16(base + KL_S  + off, g_Kl4  + gk + c);
            cp_async16(base + VTH_S + off, g_VTh4 + gv + c);
            cp_async16(base + VTL_S + off, g_VTl4 + gv + c);
        }
    };

    stage(0, 0);
    CP_COMMIT();
    __syncthreads();   // Q smem visible to all warps

    // cache Qh A-frags across ktiles
    uint32_t qhf[2][4][4];
    #pragma unroll
    for (int m = 0; m < 2; m++) {
        int mrow0 = w * 32 + m * 16;
        #pragma unroll
        for (int kc = 0; kc < 4; kc++) {
            uint32_t addr = sb + QH_OFF + (uint32_t)((mrow0 + a_row) * 128)
                          + (uint32_t)(((2 * kc + a_kh) ^ lx) << 4);
            ldsm_x4(qhf[m][kc], addr);
        }
    }

    float o[2][8][4];
    #pragma unroll
    for (int m = 0; m < 2; m++)
        #pragma unroll
        for (int n = 0; n < 8; n++)
            #pragma unroll
            for (int r = 0; r < 4; r++) o[m][n][r] = 0.0f;

    float mrunA[2] = {-1e30f, -1e30f}, mrunB[2] = {-1e30f, -1e30f};
    float lrunA[2] = {0.0f, 0.0f},     lrunB[2] = {0.0f, 0.0f};

    for (int kt = 0; kt < NKT; kt++) {
        const int p = kt & 1;
        if (kt + 1 < NKT) {
            stage(kt + 1, 1 - p);   // prefetch next tile into the other buffer
            CP_COMMIT();
            CP_WAIT(1);             // tile kt's group complete
        } else {
            CP_WAIT(0);
        }
        __syncthreads();            // staged data visible cross-warp

        const uint32_t kvb = sb + KV_OFF + p * STAGE_SZ;

        // ---- S = Q . K^T  (3 fp16 split terms), base-2 logit units ----
        float s[2][8][4];
        #pragma unroll
        for (int m = 0; m < 2; m++)
            #pragma unroll
            for (int n = 0; n < 8; n++)
                #pragma unroll
                for (int r = 0; r < 4; r++) s[m][n][r] = 0.0f;

        #pragma unroll
        for (int kc = 0; kc < 4; kc++) {
            uint32_t qlf[2][4];
            #pragma unroll
            for (int m = 0; m < 2; m++) {
                int mrow0 = w * 32 + m * 16;
                uint32_t ab = (uint32_t)((mrow0 + a_row) * 128)
                            + (uint32_t)(((2 * kc + a_kh) ^ lx) << 4);
                ldsm_x4(qlf[m], sb + QL_OFF + ab);
            }
            #pragma unroll
            for (int np = 0; np < 4; np++) {
                uint32_t bb = (uint32_t)((np * 16 + b_nr) * 128)
                            + (uint32_t)(((2 * kc + b_kh) ^ lx) << 4);
                uint32_t BH_[4], BL_[4];
                ldsm_x4(BH_, kvb + KH_S + bb);
                ldsm_x4(BL_, kvb + KL_S + bb);
                #pragma unroll
                for (int m = 0; m < 2; m++)
                    #pragma unroll
                    for (int nt = 0; nt < 2; nt++)
                        mma_f16(s[m][2 * np + nt], qhf[m][kc], BH_ + 2 * nt);
                #pragma unroll
                for (int m = 0; m < 2; m++)
                    #pragma unroll
                    for (int nt = 0; nt < 2; nt++)
                        mma_f16(s[m][2 * np + nt], qhf[m][kc], BL_ + 2 * nt);
                #pragma unroll
                for (int m = 0; m < 2; m++)
                    #pragma unroll
                    for (int nt = 0; nt < 2; nt++)
                        mma_f16(s[m][2 * np + nt], qlf[m], BH_ + 2 * nt);
            }
        }

        // ---- online softmax (base-2, MUFU ex2) ----
        float corrA[2], corrB[2];
        #pragma unroll
        for (int m = 0; m < 2; m++) {
            float mxA = -1e30f, mxB = -1e30f;
            #pragma unroll
            for (int n = 0; n < 8; n++) {
                mxA = fmaxf(mxA, fmaxf(s[m][n][0], s[m][n][1]));
                mxB = fmaxf(mxB, fmaxf(s[m][n][2], s[m][n][3]));
            }
            mxA = fmaxf(mxA, __shfl_xor_sync(0xffffffffu, mxA, 1));
            mxA = fmaxf(mxA, __shfl_xor_sync(0xffffffffu, mxA, 2));
            mxB = fmaxf(mxB, __shfl_xor_sync(0xffffffffu, mxB, 1));
            mxB = fmaxf(mxB, __shfl_xor_sync(0xffffffffu, mxB, 2));
            float mnA = fmaxf(mrunA[m], mxA);
            float mnB = fmaxf(mrunB[m], mxB);
            float cA = ex2f(mrunA[m] - mnA);
            float cB = ex2f(mrunB[m] - mnB);
            float sA = 0.0f, sB = 0.0f;
            #pragma unroll
            for (int n = 0; n < 8; n++) {
                s[m][n][0] = ex2f(s[m][n][0] - mnA); sA += s[m][n][0];
                s[m][n][1] = ex2f(s[m][n][1] - mnA); sA += s[m][n][1];
                s[m][n][2] = ex2f(s[m][n][2] - mnB); sB += s[m][n][2];
                s[m][n][3] = ex2f(s[m][n][3] - mnB); sB += s[m][n][3];
            }
            sA += __shfl_xor_sync(0xffffffffu, sA, 1);
            sA += __shfl_xor_sync(0xffffffffu, sA, 2);
            sB += __shfl_xor_sync(0xffffffffu, sB, 1);
            sB += __shfl_xor_sync(0xffffffffu, sB, 2);
            lrunA[m] = lrunA[m] * cA + sA;
            lrunB[m] = lrunB[m] * cB + sB;
            mrunA[m] = mnA;  mrunB[m] = mnB;
            corrA[m] = cA;   corrB[m] = cB;
            #pragma unroll
            for (int n = 0; n < 8; n++) {
                o[m][n][0] *= cA; o[m][n][1] *= cA;
                o[m][n][2] *= cB; o[m][n][3] *= cB;
            }
        }
        (void)corrA; (void)corrB;

        // ---- fused P-repack + PV per k-chunk (ph/pl transient) ----
        #pragma unroll
        for (int kc = 0; kc < 4; kc++) {
            uint32_t ph[2][4], pl[2][4];
            #pragma unroll
            for (int m = 0; m < 2; m++) {
                #pragma unroll
                for (int r = 0; r < 4; r++) {
                    int nsrc = 2 * kc + (r >> 1);
                    int base = (r & 1) * 2;
                    float e0 = s[m][nsrc][base + 0];
                    float e1 = s[m][nsrc][base + 1];
                    __half2 hv = __floats2half2_rn(e0, e1);
                    float2 hf2 = __half22float2(hv);
                    __half2 lv = __floats2half2_rn(e0 - hf2.x, e1 - hf2.y);
                    ph[m][r] = *(uint32_t*)&hv;
                    pl[m][r] = *(uint32_t*)&lv;
                }
            }
            #pragma unroll
            for (int np = 0; np < 4; np++) {
                uint32_t bb = (uint32_t)((np * 16 + b_nr) * 128)
                            + (uint32_t)(((2 * kc + b_kh) ^ lx) << 4);
                uint32_t BH_[4], BL_[4];
                ldsm_x4(BH_, kvb + VTH_S + bb);
                ldsm_x4(BL_, kvb + VTL_S + bb);
                #pragma unroll
                for (int m = 0; m < 2; m++)
                    #pragma unroll
                    for (int nt = 0; nt < 2; nt++)
                        mma_f16(o[m][2 * np + nt], ph[m], BH_ + 2 * nt);
                #pragma unroll
                for (int m = 0; m < 2; m++)
                    #pragma unroll
                    for (int nt = 0; nt < 2; nt++)
                        mma_f16(o[m][2 * np + nt], ph[m], BL_ + 2 * nt);
                #pragma unroll
                for (int m = 0; m < 2; m++)
                    #pragma unroll
                    for (int nt = 0; nt < 2; nt++)
                        mma_f16(o[m][2 * np + nt], pl[m], BH_ + 2 * nt);
            }
        }
        __syncthreads();   // all warps done reading buffer p before kt+2 overwrites it
    }

    // ---- epilogue: normalize, write fp32 [b, s, h*64 + d] ----
    const int b = bh >> 4, h = bh & (NH - 1);
    #pragma unroll
    for (int m = 0; m < 2; m++) {
        float invA = 1.0f / lrunA[m];
        float invB = 1.0f / lrunB[m];
        int rA = q0 + w * 32 + m * 16 + (lane >> 2);
        int rB = rA + 8;
        #pragma unroll
        for (int n = 0; n < 8; n++) {
            int col = h * HD + n * 8 + (lane & 3) * 2;
            float2 vA = make_float2(o[m][n][0] * invA, o[m][n][1] * invA);
            float2 vB = make_float2(o[m][n][2] * invB, o[m][n][3] * invB);
            *(float2*)(out + ((size_t)b * SEQ + rA) * DM + col) = vA;
            *(float2*)(out + ((size_t)b * SEQ + rB) * DM + col) = vB;
        }
    }
}

extern "C" void kernel_launch(void* const* d_in, const int* in_sizes, int n_in,
                              void* d_out, int out_size)
{
    const float* q  = (const float*)d_in[0];
    const float* k  = (const float*)d_in[1];
    const float* v  = (const float*)d_in[2];
    const float* Wq = (const float*)d_in[3];
    const float* Wk = (const float*)d_in[4];
    const float* Wv = (const float*)d_in[5];
    float* out = (float*)d_out;

    cudaFuncSetAttribute(proj_mma_kernel, cudaFuncAttributeMaxDynamicSharedMemorySize, SMEM_PROJ);
    cudaFuncSetAttribute(attn_kernel, cudaFuncAttributeMaxDynamicSharedMemorySize, SMEM_DYN);

    prep_kernel<<<2048, 256>>>(q, k, v, Wq, Wk, Wv);

    dim3 pgrid(DM / 128, (BS * SEQ) / 128, 3);
    proj_mma_kernel<<<pgrid, 256, SMEM_PROJ>>>();

    dim3 agrid(SEQ / QT, BH);
    attn_kernel<<<agrid, 128, SMEM_DYN>>>(out);
}

// round 12
// speedup vs baseline: 5.0461x; 1.1202x over previous
#include <cuda_runtime.h>
#include <cuda_fp16.h>
#include <cstdint>

#define BS   2
#define SEQ  2048
#define DM   1024
#define NH   16
#define HD   64
#define BH   (BS*NH)
// Q pre-scale: 64 * log2(e) -> logits in base-2 units, softmax via ex2.approx
#define QSCALE 92.33248261778578f
#define QT   128            // queries per CTA
#define KT   64             // keys per tile
#define NKT  (SEQ/KT)       // 32

// ---------------- fp16 split scratch (uint4 for 16B alignment) --------------
#define NELEM (BH*SEQ*HD)   // 4,194,304
__device__ uint4 g_Qh4[NELEM/8];
__device__ uint4 g_Ql4[NELEM/8];
__device__ uint4 g_Kh4[NELEM/8];
__device__ uint4 g_Kl4[NELEM/8];
__device__ uint4 g_VTh4[NELEM/8];   // V transposed: [bh][d][s]
__device__ uint4 g_VTl4[NELEM/8];

// Split inputs for projection MMA: X = {q,k,v} [3][4096][1024], W [3][1024][1024]
#define NX4 (3*4096*1024/8)
#define NW4 (3*1024*1024/8)
__device__ uint4 g_Xh4[NX4];
__device__ uint4 g_Xl4[NX4];
__device__ uint4 g_Wh4[NW4];
__device__ uint4 g_Wl4[NW4];

// ---------------- warp-MMA helpers (family-neutral PTX, sm_80+) -------------
__device__ __forceinline__ uint32_t smem_to_u32(const void* p) {
    uint32_t a;
    asm("{ .reg .u64 t; cvta.to.shared.u64 t, %1; cvt.u32.u64 %0, t; }"
        : "=r"(a) : "l"(p));
    return a;
}
__device__ __forceinline__ void ldsm_x4(uint32_t r[4], uint32_t addr) {
    asm volatile("ldmatrix.sync.aligned.m8n8.x4.shared.b16 {%0,%1,%2,%3}, [%4];"
        : "=r"(r[0]), "=r"(r[1]), "=r"(r[2]), "=r"(r[3]) : "r"(addr));
}
__device__ __forceinline__ void mma_f16(float c[4], const uint32_t a[4], const uint32_t b[2]) {
    asm volatile("mma.sync.aligned.m16n8k16.row.col.f32.f16.f16.f32 "
        "{%0,%1,%2,%3}, {%4,%5,%6,%7}, {%8,%9}, {%0,%1,%2,%3};"
        : "+f"(c[0]), "+f"(c[1]), "+f"(c[2]), "+f"(c[3])
        : "r"(a[0]), "r"(a[1]), "r"(a[2]), "r"(a[3]), "r"(b[0]), "r"(b[1]));
}
// async 16B global->shared copy (bypasses registers)
__device__ __forceinline__ void cp_async16(uint32_t smem_addr, const void* gptr) {
    asm volatile("cp.async.cg.shared.global [%0], [%1], 16;"
        :: "r"(smem_addr), "l"(__cvta_generic_to_global(gptr)) : "memory");
}
#define CP_COMMIT() asm volatile("cp.async.commit_group;" ::: "memory")
#define CP_WAIT(n)  asm volatile("cp.async.wait_group %0;" :: "n"(n) : "memory")

// 2^x on the MUFU pipe.
__device__ __forceinline__ float ex2f(float x) {
    float y;
    asm("ex2.approx.f32 %0, %1;" : "=f"(y) : "f"(x));
    return y;
}

// fp16 2-way split: x = h + l with ~2^-23 relative residual.
__device__ __forceinline__ void split2(float x, __half& h, __half& l) {
    h = __float2half_rn(x);
    l = __float2half_rn(x - __half2float(h));
}

// ---------------------------------------------------------------------------
// Prep: split X (q,k,v) and W (Wq,Wk,Wv) into fp16 h/l arrays.
// ---------------------------------------------------------------------------
__global__ __launch_bounds__(256) void prep_kernel(
    const float* __restrict__ q, const float* __restrict__ k, const float* __restrict__ v,
    const float* __restrict__ Wq, const float* __restrict__ Wk, const float* __restrict__ Wv)
{
    const int NXf4 = 3 * 4096 * 1024 / 4;     // float4 count for X
    const int NWf4 = 3 * 1024 * 1024 / 4;
    const int total = NXf4 + NWf4;
    for (int i = blockIdx.x * blockDim.x + threadIdx.x; i < total;
         i += gridDim.x * blockDim.x) {
        const float* src;
        uint2 *dh, *dl;
        int off;
        if (i < NXf4) {
            int z = i / (4096 * 1024 / 4);
            off   = i % (4096 * 1024 / 4);
            src = (z == 0) ? q : (z == 1) ? k : v;
            dh = (uint2*)g_Xh4 + i; dl = (uint2*)g_Xl4 + i;
        } else {
            int j = i - NXf4;
            int z = j / (1024 * 1024 / 4);
            off   = j % (1024 * 1024 / 4);
            src = (z == 0) ? Wq : (z == 1) ? Wk : Wv;
            dh = (uint2*)g_Wh4 + j; dl = (uint2*)g_Wl4 + j;
        }
        float4 x = ((const float4*)src)[off];
        __half h[4], l[4];
        split2(x.x, h[0], l[0]);
        split2(x.y, h[1], l[1]);
        split2(x.z, h[2], l[2]);
        split2(x.w, h[3], l[3]);
        uint2 ph, pl;
        ((__half*)&ph)[0]=h[0]; ((__half*)&ph)[1]=h[1];
        ((__half*)&ph)[2]=h[2]; ((__half*)&ph)[3]=h[3];
        ((__half*)&pl)[0]=l[0]; ((__half*)&pl)[1]=l[1];
        ((__half*)&pl)[2]=l[2]; ((__half*)&pl)[3]=l[3];
        *dh = ph; *dl = pl;
    }
}

// ---------------------------------------------------------------------------
// Projection GEMM on HMMA: Y = X @ W^T, 3-term fp16 split {hh,hl,lh}.
// (unchanged from R11 passing version)
// ---------------------------------------------------------------------------
#define XH_OFF  0
#define XL_OFF  16384
#define WH_OFF  32768
#define WL_OFF  49152
#define SMEM_PROJ 65536

__global__ void __launch_bounds__(256) proj_mma_kernel()
{
    extern __shared__ char smp[];
    const uint32_t sb = smem_to_u32(smp);
    const int tid  = threadIdx.x;
    const int w    = tid >> 5, lane = tid & 31;
    const int wm   = w & 3;
    const int wn   = w >> 2;
    const int z    = blockIdx.z;
    const int m0   = blockIdx.y * 128;
    const int n0   = blockIdx.x * 128;

    const int lx    = lane & 7;
    const int a_row = lane & 15;
    const int a_kh  = lane >> 4;
    const int b_mat = lane >> 3;
    const int b_nr  = ((b_mat >> 1) << 3) + (lane & 7);
    const int b_kh  = b_mat & 1;

    float c[2][8][4];
    #pragma unroll
    for (int m = 0; m < 2; m++)
        #pragma unroll
        for (int n = 0; n < 8; n++)
            #pragma unroll
            for (int r = 0; r < 4; r++) c[m][n][r] = 0.0f;

    for (int k0 = 0; k0 < DM; k0 += 64) {
        const int kq = k0 >> 3;
        #pragma unroll
        for (int it = 0; it < 4; it++) {
            int f = tid + it * 256;
            int r = f >> 3, ch = f & 7;
            uint32_t off = (uint32_t)(r * 128 + ((ch ^ (r & 7)) << 4));
            size_t gx = (size_t)z * 524288 + (size_t)(m0 + r) * 128 + kq + ch;
            *(uint4*)(smp + XH_OFF + off) = g_Xh4[gx];
            *(uint4*)(smp + XL_OFF + off) = g_Xl4[gx];
            size_t gw = (size_t)z * 131072 + (size_t)(n0 + r) * 128 + kq + ch;
            *(uint4*)(smp + WH_OFF + off) = g_Wh4[gw];
            *(uint4*)(smp + WL_OFF + off) = g_Wl4[gw];
        }
        __syncthreads();

        #pragma unroll
        for (int kc = 0; kc < 4; kc++) {
            uint32_t AH[2][4], AL[2][4];
            #pragma unroll
            for (int m = 0; m < 2; m++) {
                uint32_t ab = (uint32_t)((wm * 32 + m * 16 + a_row) * 128)
                            + (uint32_t)(((2 * kc + a_kh) ^ lx) << 4);
                ldsm_x4(AH[m], sb + XH_OFF + ab);
                ldsm_x4(AL[m], sb + XL_OFF + ab);
            }
            #pragma unroll
            for (int np = 0; np < 4; np++) {
                uint32_t bb = (uint32_t)((wn * 64 + np * 16 + b_nr) * 128)
                            + (uint32_t)(((2 * kc + b_kh) ^ lx) << 4);
                uint32_t BH_[4], BL_[4];
                ldsm_x4(BH_, sb + WH_OFF + bb);
                ldsm_x4(BL_, sb + WL_OFF + bb);
                #pragma unroll
                for (int m = 0; m < 2; m++)
                    #pragma unroll
                    for (int nt = 0; nt < 2; nt++)
                        mma_f16(c[m][2 * np + nt], AH[m], BH_ + 2 * nt);
                #pragma unroll
                for (int m = 0; m < 2; m++)
                    #pragma unroll
                    for (int nt = 0; nt < 2; nt++)
                        mma_f16(c[m][2 * np + nt], AH[m], BL_ + 2 * nt);
                #pragma unroll
                for (int m = 0; m < 2; m++)
                    #pragma unroll
                    for (int nt = 0; nt < 2; nt++)
                        mma_f16(c[m][2 * np + nt], AL[m], BH_ + 2 * nt);
            }
        }
        __syncthreads();
    }

    // ---- epilogue: split Y into attention operands ----
    __half* qh = (__half*)g_Qh4;   __half* ql = (__half*)g_Ql4;
    __half* kh = (__half*)g_Kh4;   __half* kl = (__half*)g_Kl4;
    __half* vth = (__half*)g_VTh4; __half* vtl = (__half*)g_VTl4;

    #pragma unroll
    for (int m = 0; m < 2; m++) {
        #pragma unroll
        for (int rr = 0; rr < 2; rr++) {
            int row = m0 + wm * 32 + m * 16 + (lane >> 2) + rr * 8;
            int b   = row >> 11;
            int s   = row & (SEQ - 1);
            #pragma unroll
            for (int n = 0; n < 8; n++) {
                int col = n0 + wn * 64 + n * 8 + (lane & 3) * 2;
                int h   = col >> 6;
                int d   = col & 63;
                int bh  = b * NH + h;
                float e0 = c[m][n][rr * 2 + 0];
                float e1 = c[m][n][rr * 2 + 1];
                if (z == 0) { e0 *= QSCALE; e1 *= QSCALE; }
                __half h0, l0, h1, l1;
                split2(e0, h0, l0);
                split2(e1, h1, l1);
                if (z != 2) {
                    size_t idx = ((size_t)bh * SEQ + s) * HD + d;
                    if (z == 0) {
                        *(__half2*)(qh + idx) = __half2(h0, h1);
                        *(__half2*)(ql + idx) = __half2(l0, l1);
                    } else {
                        *(__half2*)(kh + idx) = __half2(h0, h1);
                        *(__half2*)(kl + idx) = __half2(l0, l1);
                    }
                } else {
                    size_t idx0 = ((size_t)bh * HD + d) * SEQ + s;
                    size_t idx1 = ((size_t)bh * HD + d + 1) * SEQ + s;
                    vth[idx0] = h0; vtl[idx0] = l0;
                    vth[idx1] = h1; vtl[idx1] = l1;
                }
            }
        }
    }
}

// ---------------------------------------------------------------------------
// FA2-style attention, fp16 mma.sync. CTA = (bh, 128 q-rows).
// 256 threads = 8 warps x 16 q-rows each (halved per-warp state -> 128-reg cap
// -> 2 CTAs/SM = 16 warps/SM, matching proj's occupancy).
// cp.async double-buffered K/V staging; fused P-repack + PV.
// ---------------------------------------------------------------------------
#define QH_OFF   0
#define QL_OFF   16384
#define KV_OFF   32768
#define STAGE_SZ 32768
#define KH_S     0
#define KL_S     8192
#define VTH_S    16384
#define VTL_S    24576
#define SMEM_DYN 98304

__global__ void __launch_bounds__(256, 2) attn_kernel(float* __restrict__ out)
{
    extern __shared__ char sm[];
    const uint32_t sb = smem_to_u32(sm);
    const int tid = threadIdx.x;
    const int w = tid >> 5, lane = tid & 31;
    const int bh = blockIdx.y;
    const int q0 = blockIdx.x * QT;
    const int mrow0 = w * 16;          // this warp's 16 q-rows

    // ---- load Q (2 splits) into swizzled smem; 2 threads per 128B row ----
    {
        int r = tid >> 1, hf = tid & 1;
        size_t gq = (((size_t)bh * SEQ + q0 + r) * HD) >> 3;
        #pragma unroll
        for (int cc = 0; cc < 4; cc++) {
            int c = hf * 4 + cc;
            uint32_t off = (uint32_t)(r * 128 + ((c ^ (r & 7)) << 4));
            *(uint4*)(sm + QH_OFF + off) = g_Qh4[gq + c];
            *(uint4*)(sm + QL_OFF + off) = g_Ql4[gq + c];
        }
    }

    const int lx    = lane & 7;
    const int a_row = lane & 15;
    const int a_kh  = lane >> 4;
    const int b_mat = lane >> 3;
    const int b_nr  = ((b_mat >> 1) << 3) + (lane & 7);
    const int b_kh  = b_mat & 1;

    const int st_r  = tid >> 2, st_q = tid & 3;   // staging: 4 thr/row, 2 chunks each
    const size_t gk_base = ((size_t)bh * SEQ) * HD >> 3;
    const size_t gv_base = ((size_t)bh * HD * SEQ) >> 3;

    auto stage = [&](int kt, int p) {
        size_t gk = gk_base + ((size_t)kt * KT + st_r) * (HD / 8);
        size_t gv = gv_base + (size_t)st_r * (SEQ / 8) + (size_t)kt * (KT / 8);
        uint32_t base = sb + KV_OFF + p * STAGE_SZ;
        #pragma unroll
        for (int cc = 0; cc < 2; cc++) {
            int c = st_q * 2 + cc;
            uint32_t off = (uint32_t)(st_r * 128 + ((c ^ (st_r & 7)) << 4));
            cp_async16(base + KH_S  + off, g_Kh4  + gk + c);
            cp_async16(base + KL_S  + off, g_Kl4  + gk + c);
            cp_async16(base + VTH_S + off, g_VTh4 + gv + c);
            cp_async16(base + VTL_S + off, g_VTl4 + gv + c);
        }
    };

    stage(0, 0);
    CP_COMMIT();
    __syncthreads();   // Q smem visible to all warps

    // cache Qh A-frags across ktiles (16 rows -> one frag per k-chunk)
    uint32_t qhf[4][4];
    #pragma unroll
    for (int kc = 0; kc < 4; kc++) {
        uint32_t addr = sb + QH_OFF + (uint32_t)((mrow0 + a_row) * 128)
                      + (uint32_t)(((2 * kc + a_kh) ^ lx) << 4);
        ldsm_x4(qhf[kc], addr);
    }

    float o[8][4];
    #pragma unroll
    for (int n = 0; n < 8; n++)
        #pragma unroll
        for (int r = 0; r < 4; r++) o[n][r] = 0.0f;

    float mrunA = -1e30f, mrunB = -1e30f;
    float lrunA = 0.0f,   lrunB = 0.0f;

    for (int kt = 0; kt < NKT; kt++) {
        const int p = kt & 1;
        if (kt + 1 < NKT) {
            stage(kt + 1, 1 - p);
            CP_COMMIT();
            CP_WAIT(1);
        } else {
            CP_WAIT(0);
        }
        __syncthreads();

        const uint32_t kvb = sb + KV_OFF + p * STAGE_SZ;

        // ---- S = Q . K^T  (3 fp16 split terms), base-2 logit units ----
        float s[8][4];
        #pragma unroll
        for (int n = 0; n < 8; n++)
            #pragma unroll
            for (int r = 0; r < 4; r++) s[n][r] = 0.0f;

        #pragma unroll
        for (int kc = 0; kc < 4; kc++) {
            uint32_t qlf[4];
            {
                uint32_t ab = (uint32_t)((mrow0 + a_row) * 128)
                            + (uint32_t)(((2 * kc + a_kh) ^ lx) << 4);
                ldsm_x4(qlf, sb + QL_OFF + ab);
            }
            #pragma unroll
            for (int np = 0; np < 4; np++) {
                uint32_t bb = (uint32_t)((np * 16 + b_nr) * 128)
                            + (uint32_t)(((2 * kc + b_kh) ^ lx) << 4);
                uint32_t BH_[4], BL_[4];
                ldsm_x4(BH_, kvb + KH_S + bb);
                ldsm_x4(BL_, kvb + KL_S + bb);
                #pragma unroll
                for (int nt = 0; nt < 2; nt++)
                    mma_f16(s[2 * np + nt], qhf[kc], BH_ + 2 * nt);
                #pragma unroll
                for (int nt = 0; nt < 2; nt++)
                    mma_f16(s[2 * np + nt], qhf[kc], BL_ + 2 * nt);
                #pragma unroll
                for (int nt = 0; nt < 2; nt++)
                    mma_f16(s[2 * np + nt], qlf, BH_ + 2 * nt);
            }
        }

        // ---- online softmax (base-2, MUFU ex2) ----
        {
            float mxA = -1e30f, mxB = -1e30f;
            #pragma unroll
            for (int n = 0; n < 8; n++) {
                mxA = fmaxf(mxA, fmaxf(s[n][0], s[n][1]));
                mxB = fmaxf(mxB, fmaxf(s[n][2], s[n][3]));
            }
            mxA = fmaxf(mxA, __shfl_xor_sync(0xffffffffu, mxA, 1));
            mxA = fmaxf(mxA, __shfl_xor_sync(0xffffffffu, mxA, 2));
            mxB = fmaxf(mxB, __shfl_xor_sync(0xffffffffu, mxB, 1));
            mxB = fmaxf(mxB, __shfl_xor_sync(0xffffffffu, mxB, 2));
            float mnA = fmaxf(mrunA, mxA);
            float mnB = fmaxf(mrunB, mxB);
            float cA = ex2f(mrunA - mnA);
            float cB = ex2f(mrunB - mnB);
            float sA = 0.0f, sB = 0.0f;
            #pragma unroll
            for (int n = 0; n < 8; n++) {
                s[n][0] = ex2f(s[n][0] - mnA); sA += s[n][0];
                s[n][1] = ex2f(s[n][1] - mnA); sA += s[n][1];
                s[n][2] = ex2f(s[n][2] - mnB); sB += s[n][2];
                s[n][3] = ex2f(s[n][3] - mnB); sB += s[n][3];
            }
            sA += __shfl_xor_sync(0xffffffffu, sA, 1);
            sA += __shfl_xor_sync(0xffffffffu, sA, 2);
            sB += __shfl_xor_sync(0xffffffffu, sB, 1);
            sB += __shfl_xor_sync(0xffffffffu, sB, 2);
            lrunA = lrunA * cA + sA;
            lrunB = lrunB * cB + sB;
            mrunA = mnA;  mrunB = mnB;
            #pragma unroll
            for (int n = 0; n < 8; n++) {
                o[n][0] *= cA; o[n][1] *= cA;
                o[n][2] *= cB; o[n][3] *= cB;
            }
        }

        // ---- fused P-repack + PV per k-chunk (ph/pl transient) ----
        #pragma unroll
        for (int kc = 0; kc < 4; kc++) {
            uint32_t ph[4], pl[4];
            #pragma unroll
            for (int r = 0; r < 4; r++) {
                int nsrc = 2 * kc + (r >> 1);
                int base = (r & 1) * 2;
                float e0 = s[nsrc][base + 0];
                float e1 = s[nsrc][base + 1];
                __half2 hv = __floats2half2_rn(e0, e1);
                float2 hf2 = __half22float2(hv);
                __half2 lv = __floats2half2_rn(e0 - hf2.x, e1 - hf2.y);
                ph[r] = *(uint32_t*)&hv;
                pl[r] = *(uint32_t*)&lv;
            }
            #pragma unroll
            for (int np = 0; np < 4; np++) {
                uint32_t bb = (uint32_t)((np * 16 + b_nr) * 128)
                            + (uint32_t)(((2 * kc + b_kh) ^ lx) << 4);
                uint32_t BH_[4], BL_[4];
                ldsm_x4(BH_, kvb + VTH_S + bb);
                ldsm_x4(BL_, kvb + VTL_S + bb);
                #pragma unroll
                for (int nt = 0; nt < 2; nt++)
                    mma_f16(o[2 * np + nt], ph, BH_ + 2 * nt);
                #pragma unroll
                for (int nt = 0; nt < 2; nt++)
                    mma_f16(o[2 * np + nt], ph, BL_ + 2 * nt);
                #pragma unroll
                for (int nt = 0; nt < 2; nt++)
                    mma_f16(o[2 * np + nt], pl, BH_ + 2 * nt);
            }
        }
        __syncthreads();   // all warps done reading buffer p before overwrite
    }

    // ---- epilogue: normalize, write fp32 [b, s, h*64 + d] ----
    const int b = bh >> 4, h = bh & (NH - 1);
    {
        float invA = 1.0f / lrunA;
        float invB = 1.0f / lrunB;
        int rA = q0 + mrow0 + (lane >> 2);
        int rB = rA + 8;
        #pragma unroll
        for (int n = 0; n < 8; n++) {
            int col = h * HD + n * 8 + (lane & 3) * 2;
            float2 vA = make_float2(o[n][0] * invA, o[n][1] * invA);
            float2 vB = make_float2(o[n][2] * invB, o[n][3] * invB);
            *(float2*)(out + ((size_t)b * SEQ + rA) * DM + col) = vA;
            *(float2*)(out + ((size_t)b * SEQ + rB) * DM + col) = vB;
        }
    }
}

extern "C" void kernel_launch(void* const* d_in, const int* in_sizes, int n_in,
                              void* d_out, int out_size)
{
    const float* q  = (const float*)d_in[0];
    const float* k  = (const float*)d_in[1];
    const float* v  = (const float*)d_in[2];
    const float* Wq = (const float*)d_in[3];
    const float* Wk = (const float*)d_in[4];
    const float* Wv = (const float*)d_in[5];
    float* out = (float*)d_out;

    cudaFuncSetAttribute(proj_mma_kernel, cudaFuncAttributeMaxDynamicSharedMemorySize, SMEM_PROJ);
    cudaFuncSetAttribute(attn_kernel, cudaFuncAttributeMaxDynamicSharedMemorySize, SMEM_DYN);

    prep_kernel<<<2048, 256>>>(q, k, v, Wq, Wk, Wv);

    dim3 pgrid(DM / 128, (BS * SEQ) / 128, 3);
    proj_mma_kernel<<<pgrid, 256, SMEM_PROJ>>>();

    dim3 agrid(SEQ / QT, BH);
    attn_kernel<<<agrid, 256, SMEM_DYN>>>(out);
}

// round 13
// speedup vs baseline: 5.4815x; 1.0863x over previous
#include <cuda_runtime.h>
#include <cuda_fp16.h>
#include <cstdint>

#define BS   2
#define SEQ  2048
#define DM   1024
#define NH   16
#define HD   64
#define BH   (BS*NH)
// Q pre-scale: 64 * log2(e) -> logits in base-2 units, softmax via ex2.approx
#define QSCALE 92.33248261778578f
#define QT   128            // queries per CTA
#define KT   64             // keys per tile
#define NKT  (SEQ/KT)       // 32

// ---------------- fp16 split scratch (uint4 for 16B alignment) --------------
#define NELEM (BH*SEQ*HD)   // 4,194,304
__device__ uint4 g_Qh4[NELEM/8];
__device__ uint4 g_Ql4[NELEM/8];
__device__ uint4 g_Kh4[NELEM/8];
__device__ uint4 g_Kl4[NELEM/8];
__device__ uint4 g_VTh4[NELEM/8];   // V transposed: [bh][d][s]
__device__ uint4 g_VTl4[NELEM/8];

// Split inputs for projection MMA: X = {q,k,v} [3][4096][1024], W [3][1024][1024]
#define NX4 (3*4096*1024/8)
#define NW4 (3*1024*1024/8)
__device__ uint4 g_Xh4[NX4];
__device__ uint4 g_Xl4[NX4];
__device__ uint4 g_Wh4[NW4];
__device__ uint4 g_Wl4[NW4];

// ---------------- warp-MMA helpers (family-neutral PTX, sm_80+) -------------
__device__ __forceinline__ uint32_t smem_to_u32(const void* p) {
    uint32_t a;
    asm("{ .reg .u64 t; cvta.to.shared.u64 t, %1; cvt.u32.u64 %0, t; }"
        : "=r"(a) : "l"(p));
    return a;
}
__device__ __forceinline__ void ldsm_x4(uint32_t r[4], uint32_t addr) {
    asm volatile("ldmatrix.sync.aligned.m8n8.x4.shared.b16 {%0,%1,%2,%3}, [%4];"
        : "=r"(r[0]), "=r"(r[1]), "=r"(r[2]), "=r"(r[3]) : "r"(addr));
}
__device__ __forceinline__ void mma_f16(float c[4], const uint32_t a[4], const uint32_t b[2]) {
    asm volatile("mma.sync.aligned.m16n8k16.row.col.f32.f16.f16.f32 "
        "{%0,%1,%2,%3}, {%4,%5,%6,%7}, {%8,%9}, {%0,%1,%2,%3};"
        : "+f"(c[0]), "+f"(c[1]), "+f"(c[2]), "+f"(c[3])
        : "r"(a[0]), "r"(a[1]), "r"(a[2]), "r"(a[3]), "r"(b[0]), "r"(b[1]));
}
// async 16B global->shared copy (bypasses registers)
__device__ __forceinline__ void cp_async16(uint32_t smem_addr, const void* gptr) {
    asm volatile("cp.async.cg.shared.global [%0], [%1], 16;"
        :: "r"(smem_addr), "l"(__cvta_generic_to_global(gptr)) : "memory");
}
#define CP_COMMIT() asm volatile("cp.async.commit_group;" ::: "memory")
#define CP_WAIT(n)  asm volatile("cp.async.wait_group %0;" :: "n"(n) : "memory")

// 2^x on the MUFU pipe.
__device__ __forceinline__ float ex2f(float x) {
    float y;
    asm("ex2.approx.f32 %0, %1;" : "=f"(y) : "f"(x));
    return y;
}

// fp16 2-way split: x = h + l with ~2^-23 relative residual.
__device__ __forceinline__ void split2(float x, __half& h, __half& l) {
    h = __float2half_rn(x);
    l = __float2half_rn(x - __half2float(h));
}

// ---------------------------------------------------------------------------
// Prep: split X (q,k,v) and W (Wq,Wk,Wv) into fp16 h/l arrays.
// ---------------------------------------------------------------------------
__global__ __launch_bounds__(256) void prep_kernel(
    const float* __restrict__ q, const float* __restrict__ k, const float* __restrict__ v,
    const float* __restrict__ Wq, const float* __restrict__ Wk, const float* __restrict__ Wv)
{
    const int NXf4 = 3 * 4096 * 1024 / 4;     // float4 count for X
    const int NWf4 = 3 * 1024 * 1024 / 4;
    const int total = NXf4 + NWf4;
    for (int i = blockIdx.x * blockDim.x + threadIdx.x; i < total;
         i += gridDim.x * blockDim.x) {
        const float* src;
        uint2 *dh, *dl;
        int off;
        if (i < NXf4) {
            int z = i / (4096 * 1024 / 4);
            off   = i % (4096 * 1024 / 4);
            src = (z == 0) ? q : (z == 1) ? k : v;
            dh = (uint2*)g_Xh4 + i; dl = (uint2*)g_Xl4 + i;
        } else {
            int j = i - NXf4;
            int z = j / (1024 * 1024 / 4);
            off   = j % (1024 * 1024 / 4);
            src = (z == 0) ? Wq : (z == 1) ? Wk : Wv;
            dh = (uint2*)g_Wh4 + j; dl = (uint2*)g_Wl4 + j;
        }
        float4 x = ((const float4*)src)[off];
        __half h[4], l[4];
        split2(x.x, h[0], l[0]);
        split2(x.y, h[1], l[1]);
        split2(x.z, h[2], l[2]);
        split2(x.w, h[3], l[3]);
        uint2 ph, pl;
        ((__half*)&ph)[0]=h[0]; ((__half*)&ph)[1]=h[1];
        ((__half*)&ph)[2]=h[2]; ((__half*)&ph)[3]=h[3];
        ((__half*)&pl)[0]=l[0]; ((__half*)&pl)[1]=l[1];
        ((__half*)&pl)[2]=l[2]; ((__half*)&pl)[3]=l[3];
        *dh = ph; *dl = pl;
    }
}

// ---------------------------------------------------------------------------
// Projection GEMM on HMMA: Y = X @ W^T, 3-term fp16 split {hh,hl,lh}.
// (unchanged from R12 passing version)
// ---------------------------------------------------------------------------
#define XH_OFF  0
#define XL_OFF  16384
#define WH_OFF  32768
#define WL_OFF  49152
#define SMEM_PROJ 65536

__global__ void __launch_bounds__(256) proj_mma_kernel()
{
    extern __shared__ char smp[];
    const uint32_t sb = smem_to_u32(smp);
    const int tid  = threadIdx.x;
    const int w    = tid >> 5, lane = tid & 31;
    const int wm   = w & 3;
    const int wn   = w >> 2;
    const int z    = blockIdx.z;
    const int m0   = blockIdx.y * 128;
    const int n0   = blockIdx.x * 128;

    const int lx    = lane & 7;
    const int a_row = lane & 15;
    const int a_kh  = lane >> 4;
    const int b_mat = lane >> 3;
    const int b_nr  = ((b_mat >> 1) << 3) + (lane & 7);
    const int b_kh  = b_mat & 1;

    float c[2][8][4];
    #pragma unroll
    for (int m = 0; m < 2; m++)
        #pragma unroll
        for (int n = 0; n < 8; n++)
            #pragma unroll
            for (int r = 0; r < 4; r++) c[m][n][r] = 0.0f;

    for (int k0 = 0; k0 < DM; k0 += 64) {
        const int kq = k0 >> 3;
        #pragma unroll
        for (int it = 0; it < 4; it++) {
            int f = tid + it * 256;
            int r = f >> 3, ch = f & 7;
            uint32_t off = (uint32_t)(r * 128 + ((ch ^ (r & 7)) << 4));
            size_t gx = (size_t)z * 524288 + (size_t)(m0 + r) * 128 + kq + ch;
            *(uint4*)(smp + XH_OFF + off) = g_Xh4[gx];
            *(uint4*)(smp + XL_OFF + off) = g_Xl4[gx];
            size_t gw = (size_t)z * 131072 + (size_t)(n0 + r) * 128 + kq + ch;
            *(uint4*)(smp + WH_OFF + off) = g_Wh4[gw];
            *(uint4*)(smp + WL_OFF + off) = g_Wl4[gw];
        }
        __syncthreads();

        #pragma unroll
        for (int kc = 0; kc < 4; kc++) {
            uint32_t AH[2][4], AL[2][4];
            #pragma unroll
            for (int m = 0; m < 2; m++) {
                uint32_t ab = (uint32_t)((wm * 32 + m * 16 + a_row) * 128)
                            + (uint32_t)(((2 * kc + a_kh) ^ lx) << 4);
                ldsm_x4(AH[m], sb + XH_OFF + ab);
                ldsm_x4(AL[m], sb + XL_OFF + ab);
            }
            #pragma unroll
            for (int np = 0; np < 4; np++) {
                uint32_t bb = (uint32_t)((wn * 64 + np * 16 + b_nr) * 128)
                            + (uint32_t)(((2 * kc + b_kh) ^ lx) << 4);
                uint32_t BH_[4], BL_[4];
                ldsm_x4(BH_, sb + WH_OFF + bb);
                ldsm_x4(BL_, sb + WL_OFF + bb);
                #pragma unroll
                for (int m = 0; m < 2; m++)
                    #pragma unroll
                    for (int nt = 0; nt < 2; nt++)
                        mma_f16(c[m][2 * np + nt], AH[m], BH_ + 2 * nt);
                #pragma unroll
                for (int m = 0; m < 2; m++)
                    #pragma unroll
                    for (int nt = 0; nt < 2; nt++)
                        mma_f16(c[m][2 * np + nt], AH[m], BL_ + 2 * nt);
                #pragma unroll
                for (int m = 0; m < 2; m++)
                    #pragma unroll
                    for (int nt = 0; nt < 2; nt++)
                        mma_f16(c[m][2 * np + nt], AL[m], BH_ + 2 * nt);
            }
        }
        __syncthreads();
    }

    // ---- epilogue: split Y into attention operands ----
    __half* qh = (__half*)g_Qh4;   __half* ql = (__half*)g_Ql4;
    __half* kh = (__half*)g_Kh4;   __half* kl = (__half*)g_Kl4;
    __half* vth = (__half*)g_VTh4; __half* vtl = (__half*)g_VTl4;

    #pragma unroll
    for (int m = 0; m < 2; m++) {
        #pragma unroll
        for (int rr = 0; rr < 2; rr++) {
            int row = m0 + wm * 32 + m * 16 + (lane >> 2) + rr * 8;
            int b   = row >> 11;
            int s   = row & (SEQ - 1);
            #pragma unroll
            for (int n = 0; n < 8; n++) {
                int col = n0 + wn * 64 + n * 8 + (lane & 3) * 2;
                int h   = col >> 6;
                int d   = col & 63;
                int bh  = b * NH + h;
                float e0 = c[m][n][rr * 2 + 0];
                float e1 = c[m][n][rr * 2 + 1];
                if (z == 0) { e0 *= QSCALE; e1 *= QSCALE; }
                __half h0, l0, h1, l1;
                split2(e0, h0, l0);
                split2(e1, h1, l1);
                if (z != 2) {
                    size_t idx = ((size_t)bh * SEQ + s) * HD + d;
                    if (z == 0) {
                        *(__half2*)(qh + idx) = __half2(h0, h1);
                        *(__half2*)(ql + idx) = __half2(l0, l1);
                    } else {
                        *(__half2*)(kh + idx) = __half2(h0, h1);
                        *(__half2*)(kl + idx) = __half2(l0, l1);
                    }
                } else {
                    size_t idx0 = ((size_t)bh * HD + d) * SEQ + s;
                    size_t idx1 = ((size_t)bh * HD + d + 1) * SEQ + s;
                    vth[idx0] = h0; vtl[idx0] = l0;
                    vth[idx1] = h1; vtl[idx1] = l1;
                }
            }
        }
    }
}

// ---------------------------------------------------------------------------
// FA2-style attention, fp16 mma.sync. CTA = (bh, 128 q-rows).
// 256 threads = 8 warps x 16 q-rows; 2 CTAs/SM = 16 warps/SM.
// cp.async double-buffered K/V staging.
// PV uses fp16-rounded P only (2 terms {ph.vh, ph.vl}); normalizer stays fp32.
// ---------------------------------------------------------------------------
#define QH_OFF   0
#define QL_OFF   16384
#define KV_OFF   32768
#define STAGE_SZ 32768
#define KH_S     0
#define KL_S     8192
#define VTH_S    16384
#define VTL_S    24576
#define SMEM_DYN 98304

__global__ void __launch_bounds__(256, 2) attn_kernel(float* __restrict__ out)
{
    extern __shared__ char sm[];
    const uint32_t sb = smem_to_u32(sm);
    const int tid = threadIdx.x;
    const int w = tid >> 5, lane = tid & 31;
    const int bh = blockIdx.y;
    const int q0 = blockIdx.x * QT;
    const int mrow0 = w * 16;          // this warp's 16 q-rows

    // ---- load Q (2 splits) into swizzled smem; 2 threads per 128B row ----
    {
        int r = tid >> 1, hf = tid & 1;
        size_t gq = (((size_t)bh * SEQ + q0 + r) * HD) >> 3;
        #pragma unroll
        for (int cc = 0; cc < 4; cc++) {
            int c = hf * 4 + cc;
            uint32_t off = (uint32_t)(r * 128 + ((c ^ (r & 7)) << 4));
            *(uint4*)(sm + QH_OFF + off) = g_Qh4[gq + c];
            *(uint4*)(sm + QL_OFF + off) = g_Ql4[gq + c];
        }
    }

    const int lx    = lane & 7;
    const int a_row = lane & 15;
    const int a_kh  = lane >> 4;
    const int b_mat = lane >> 3;
    const int b_nr  = ((b_mat >> 1) << 3) + (lane & 7);
    const int b_kh  = b_mat & 1;

    const int st_r  = tid >> 2, st_q = tid & 3;   // staging: 4 thr/row, 2 chunks each
    const size_t gk_base = ((size_t)bh * SEQ) * HD >> 3;
    const size_t gv_base = ((size_t)bh * HD * SEQ) >> 3;

    auto stage = [&](int kt, int p) {
        size_t gk = gk_base + ((size_t)kt * KT + st_r) * (HD / 8);
        size_t gv = gv_base + (size_t)st_r * (SEQ / 8) + (size_t)kt * (KT / 8);
        uint32_t base = sb + KV_OFF + p * STAGE_SZ;
        #pragma unroll
        for (int cc = 0; cc < 2; cc++) {
            int c = st_q * 2 + cc;
            uint32_t off = (uint32_t)(st_r * 128 + ((c ^ (st_r & 7)) << 4));
            cp_async16(base + KH_S  + off, g_Kh4  + gk + c);
            cp_async16(base + KL_S  + off, g_Kl4  + gk + c);
            cp_async16(base + VTH_S + off, g_VTh4 + gv + c);
            cp_async16(base + VTL_S + off, g_VTl4 + gv + c);
        }
    };

    stage(0, 0);
    CP_COMMIT();
    __syncthreads();   // Q smem visible to all warps

    // cache Qh A-frags across ktiles (16 rows -> one frag per k-chunk)
    uint32_t qhf[4][4];
    #pragma unroll
    for (int kc = 0; kc < 4; kc++) {
        uint32_t addr = sb + QH_OFF + (uint32_t)((mrow0 + a_row) * 128)
                      + (uint32_t)(((2 * kc + a_kh) ^ lx) << 4);
        ldsm_x4(qhf[kc], addr);
    }

    float o[8][4];
    #pragma unroll
    for (int n = 0; n < 8; n++)
        #pragma unroll
        for (int r = 0; r < 4; r++) o[n][r] = 0.0f;

    float mrunA = -1e30f, mrunB = -1e30f;
    float lrunA = 0.0f,   lrunB = 0.0f;

    for (int kt = 0; kt < NKT; kt++) {
        const int p = kt & 1;
        if (kt + 1 < NKT) {
            stage(kt + 1, 1 - p);
            CP_COMMIT();
            CP_WAIT(1);
        } else {
            CP_WAIT(0);
        }
        __syncthreads();

        const uint32_t kvb = sb + KV_OFF + p * STAGE_SZ;

        // ---- S = Q . K^T  (3 fp16 split terms), base-2 logit units ----
        float s[8][4];
        #pragma unroll
        for (int n = 0; n < 8; n++)
            #pragma unroll
            for (int r = 0; r < 4; r++) s[n][r] = 0.0f;

        #pragma unroll
        for (int kc = 0; kc < 4; kc++) {
            uint32_t qlf[4];
            {
                uint32_t ab = (uint32_t)((mrow0 + a_row) * 128)
                            + (uint32_t)(((2 * kc + a_kh) ^ lx) << 4);
                ldsm_x4(qlf, sb + QL_OFF + ab);
            }
            #pragma unroll
            for (int np = 0; np < 4; np++) {
                uint32_t bb = (uint32_t)((np * 16 + b_nr) * 128)
                            + (uint32_t)(((2 * kc + b_kh) ^ lx) << 4);
                uint32_t BH_[4], BL_[4];
                ldsm_x4(BH_, kvb + KH_S + bb);
                ldsm_x4(BL_, kvb + KL_S + bb);
                #pragma unroll
                for (int nt = 0; nt < 2; nt++)
                    mma_f16(s[2 * np + nt], qhf[kc], BH_ + 2 * nt);
                #pragma unroll
                for (int nt = 0; nt < 2; nt++)
                    mma_f16(s[2 * np + nt], qhf[kc], BL_ + 2 * nt);
                #pragma unroll
                for (int nt = 0; nt < 2; nt++)
                    mma_f16(s[2 * np + nt], qlf, BH_ + 2 * nt);
            }
        }

        // ---- online softmax (base-2, MUFU ex2) ----
        {
            float mxA = -1e30f, mxB = -1e30f;
            #pragma unroll
            for (int n = 0; n < 8; n++) {
                mxA = fmaxf(mxA, fmaxf(s[n][0], s[n][1]));
                mxB = fmaxf(mxB, fmaxf(s[n][2], s[n][3]));
            }
            mxA = fmaxf(mxA, __shfl_xor_sync(0xffffffffu, mxA, 1));
            mxA = fmaxf(mxA, __shfl_xor_sync(0xffffffffu, mxA, 2));
            mxB = fmaxf(mxB, __shfl_xor_sync(0xffffffffu, mxB, 1));
            mxB = fmaxf(mxB, __shfl_xor_sync(0xffffffffu, mxB, 2));
            float mnA = fmaxf(mrunA, mxA);
            float mnB = fmaxf(mrunB, mxB);
            float cA = ex2f(mrunA - mnA);
            float cB = ex2f(mrunB - mnB);
            float sA = 0.0f, sB = 0.0f;
            #pragma unroll
            for (int n = 0; n < 8; n++) {
                s[n][0] = ex2f(s[n][0] - mnA); sA += s[n][0];
                s[n][1] = ex2f(s[n][1] - mnA); sA += s[n][1];
                s[n][2] = ex2f(s[n][2] - mnB); sB += s[n][2];
                s[n][3] = ex2f(s[n][3] - mnB); sB += s[n][3];
            }
            sA += __shfl_xor_sync(0xffffffffu, sA, 1);
            sA += __shfl_xor_sync(0xffffffffu, sA, 2);
            sB += __shfl_xor_sync(0xffffffffu, sB, 1);
            sB += __shfl_xor_sync(0xffffffffu, sB, 2);
            lrunA = lrunA * cA + sA;
            lrunB = lrunB * cB + sB;
            mrunA = mnA;  mrunB = mnB;
            #pragma unroll
            for (int n = 0; n < 8; n++) {
                o[n][0] *= cA; o[n][1] *= cA;
                o[n][2] *= cB; o[n][3] *= cB;
            }
        }

        // ---- fused P-pack + PV per k-chunk (fp16 P only; 2 terms) ----
        #pragma unroll
        for (int kc = 0; kc < 4; kc++) {
            uint32_t ph[4];
            #pragma unroll
            for (int r = 0; r < 4; r++) {
                int nsrc = 2 * kc + (r >> 1);
                int base = (r & 1) * 2;
                __half2 hv = __floats2half2_rn(s[nsrc][base + 0], s[nsrc][base + 1]);
                ph[r] = *(uint32_t*)&hv;
            }
            #pragma unroll
            for (int np = 0; np < 4; np++) {
                uint32_t bb = (uint32_t)((np * 16 + b_nr) * 128)
                            + (uint32_t)(((2 * kc + b_kh) ^ lx) << 4);
                uint32_t BH_[4], BL_[4];
                ldsm_x4(BH_, kvb + VTH_S + bb);
                ldsm_x4(BL_, kvb + VTL_S + bb);
                #pragma unroll
                for (int nt = 0; nt < 2; nt++)
                    mma_f16(o[2 * np + nt], ph, BH_ + 2 * nt);
                #pragma unroll
                for (int nt = 0; nt < 2; nt++)
                    mma_f16(o[2 * np + nt], ph, BL_ + 2 * nt);
            }
        }
        __syncthreads();   // all warps done reading buffer p before overwrite
    }

    // ---- epilogue: normalize, write fp32 [b, s, h*64 + d] ----
    const int b = bh >> 4, h = bh & (NH - 1);
    {
        float invA = 1.0f / lrunA;
        float invB = 1.0f / lrunB;
        int rA = q0 + mrow0 + (lane >> 2);
        int rB = rA + 8;
        #pragma unroll
        for (int n = 0; n < 8; n++) {
            int col = h * HD + n * 8 + (lane & 3) * 2;
            float2 vA = make_float2(o[n][0] * invA, o[n][1] * invA);
            float2 vB = make_float2(o[n][2] * invB, o[n][3] * invB);
            *(float2*)(out + ((size_t)b * SEQ + rA) * DM + col) = vA;
            *(float2*)(out + ((size_t)b * SEQ + rB) * DM + col) = vB;
        }
    }
}

extern "C" void kernel_launch(void* const* d_in, const int* in_sizes, int n_in,
                              void* d_out, int out_size)
{
    const float* q  = (const float*)d_in[0];
    const float* k  = (const float*)d_in[1];
    const float* v  = (const float*)d_in[2];
    const float* Wq = (const float*)d_in[3];
    const float* Wk = (const float*)d_in[4];
    const float* Wv = (const float*)d_in[5];
    float* out = (float*)d_out;

    cudaFuncSetAttribute(proj_mma_kernel, cudaFuncAttributeMaxDynamicSharedMemorySize, SMEM_PROJ);
    cudaFuncSetAttribute(attn_kernel, cudaFuncAttributeMaxDynamicSharedMemorySize, SMEM_DYN);

    prep_kernel<<<2048, 256>>>(q, k, v, Wq, Wk, Wv);

    dim3 pgrid(DM / 128, (BS * SEQ) / 128, 3);
    proj_mma_kernel<<<pgrid, 256, SMEM_PROJ>>>();

    dim3 agrid(SEQ / QT, BH);
    attn_kernel<<<agrid, 256, SMEM_DYN>>>(out);
}

// round 14
// speedup vs baseline: 5.9648x; 1.0882x over previous
#include <cuda_runtime.h>
#include <cuda_fp16.h>
#include <cstdint>

#define BS   2
#define SEQ  2048
#define DM   1024
#define NH   16
#define HD   64
#define BH   (BS*NH)
// Q pre-scale: 64 * log2(e) -> logits in base-2 units, softmax via ex2.approx
#define QSCALE 92.33248261778578f
#define QT   128            // queries per CTA
#define KT   64             // keys per tile
#define NKT  (SEQ/KT)       // 32

// ---------------- fp16 split scratch (uint4 for 16B alignment) --------------
#define NELEM (BH*SEQ*HD)   // 4,194,304
__device__ uint4 g_Qh4[NELEM/8];
__device__ uint4 g_Ql4[NELEM/8];
__device__ uint4 g_Kh4[NELEM/8];
__device__ uint4 g_Kl4[NELEM/8];
__device__ uint4 g_VTh4[NELEM/8];   // V transposed: [bh][d][s], single fp16

// Split inputs for projection MMA: X = {q,k,v} [3][4096][1024], W [3][1024][1024]
#define NX4 (3*4096*1024/8)
#define NW4 (3*1024*1024/8)
__device__ uint4 g_Xh4[NX4];
__device__ uint4 g_Xl4[NX4];
__device__ uint4 g_Wh4[NW4];
__device__ uint4 g_Wl4[NW4];

// ---------------- warp-MMA helpers (family-neutral PTX, sm_80+) -------------
__device__ __forceinline__ uint32_t smem_to_u32(const void* p) {
    uint32_t a;
    asm("{ .reg .u64 t; cvta.to.shared.u64 t, %1; cvt.u32.u64 %0, t; }"
        : "=r"(a) : "l"(p));
    return a;
}
__device__ __forceinline__ void ldsm_x4(uint32_t r[4], uint32_t addr) {
    asm volatile("ldmatrix.sync.aligned.m8n8.x4.shared.b16 {%0,%1,%2,%3}, [%4];"
        : "=r"(r[0]), "=r"(r[1]), "=r"(r[2]), "=r"(r[3]) : "r"(addr));
}
__device__ __forceinline__ void mma_f16(float c[4], const uint32_t a[4], const uint32_t b[2]) {
    asm volatile("mma.sync.aligned.m16n8k16.row.col.f32.f16.f16.f32 "
        "{%0,%1,%2,%3}, {%4,%5,%6,%7}, {%8,%9}, {%0,%1,%2,%3};"
        : "+f"(c[0]), "+f"(c[1]), "+f"(c[2]), "+f"(c[3])
        : "r"(a[0]), "r"(a[1]), "r"(a[2]), "r"(a[3]), "r"(b[0]), "r"(b[1]));
}
// async 16B global->shared copy (bypasses registers)
__device__ __forceinline__ void cp_async16(uint32_t smem_addr, const void* gptr) {
    asm volatile("cp.async.cg.shared.global [%0], [%1], 16;"
        :: "r"(smem_addr), "l"(__cvta_generic_to_global(gptr)) : "memory");
}
#define CP_COMMIT() asm volatile("cp.async.commit_group;" ::: "memory")
#define CP_WAIT(n)  asm volatile("cp.async.wait_group %0;" :: "n"(n) : "memory")

// 2^x on the MUFU pipe.
__device__ __forceinline__ float ex2f(float x) {
    float y;
    asm("ex2.approx.f32 %0, %1;" : "=f"(y) : "f"(x));
    return y;
}

// fp16 2-way split: x = h + l with ~2^-23 relative residual.
__device__ __forceinline__ void split2(float x, __half& h, __half& l) {
    h = __float2half_rn(x);
    l = __float2half_rn(x - __half2float(h));
}

// ---------------------------------------------------------------------------
// Prep: split X (q,k,v) and W (Wq,Wk,Wv) into fp16 h/l arrays.
// ---------------------------------------------------------------------------
__global__ __launch_bounds__(256) void prep_kernel(
    const float* __restrict__ q, const float* __restrict__ k, const float* __restrict__ v,
    const float* __restrict__ Wq, const float* __restrict__ Wk, const float* __restrict__ Wv)
{
    const int NXf4 = 3 * 4096 * 1024 / 4;     // float4 count for X
    const int NWf4 = 3 * 1024 * 1024 / 4;
    const int total = NXf4 + NWf4;
    for (int i = blockIdx.x * blockDim.x + threadIdx.x; i < total;
         i += gridDim.x * blockDim.x) {
        const float* src;
        uint2 *dh, *dl;
        int off;
        if (i < NXf4) {
            int z = i / (4096 * 1024 / 4);
            off   = i % (4096 * 1024 / 4);
            src = (z == 0) ? q : (z == 1) ? k : v;
            dh = (uint2*)g_Xh4 + i; dl = (uint2*)g_Xl4 + i;
        } else {
            int j = i - NXf4;
            int z = j / (1024 * 1024 / 4);
            off   = j % (1024 * 1024 / 4);
            src = (z == 0) ? Wq : (z == 1) ? Wk : Wv;
            dh = (uint2*)g_Wh4 + j; dl = (uint2*)g_Wl4 + j;
        }
        float4 x = ((const float4*)src)[off];
        __half h[4], l[4];
        split2(x.x, h[0], l[0]);
        split2(x.y, h[1], l[1]);
        split2(x.z, h[2], l[2]);
        split2(x.w, h[3], l[3]);
        uint2 ph, pl;
        ((__half*)&ph)[0]=h[0]; ((__half*)&ph)[1]=h[1];
        ((__half*)&ph)[2]=h[2]; ((__half*)&ph)[3]=h[3];
        ((__half*)&pl)[0]=l[0]; ((__half*)&pl)[1]=l[1];
        ((__half*)&pl)[2]=l[2]; ((__half*)&pl)[3]=l[3];
        *dh = ph; *dl = pl;
    }
}

// ---------------------------------------------------------------------------
// Projection GEMM on HMMA: Y = X @ W^T, 3-term fp16 split {hh,hl,lh}.
// Epilogue: Q x QSCALE 2-way split, K 2-way split, VT single fp16.
// ---------------------------------------------------------------------------
#define XH_OFF  0
#define XL_OFF  16384
#define WH_OFF  32768
#define WL_OFF  49152
#define SMEM_PROJ 65536

__global__ void __launch_bounds__(256) proj_mma_kernel()
{
    extern __shared__ char smp[];
    const uint32_t sb = smem_to_u32(smp);
    const int tid  = threadIdx.x;
    const int w    = tid >> 5, lane = tid & 31;
    const int wm   = w & 3;
    const int wn   = w >> 2;
    const int z    = blockIdx.z;
    const int m0   = blockIdx.y * 128;
    const int n0   = blockIdx.x * 128;

    const int lx    = lane & 7;
    const int a_row = lane & 15;
    const int a_kh  = lane >> 4;
    const int b_mat = lane >> 3;
    const int b_nr  = ((b_mat >> 1) << 3) + (lane & 7);
    const int b_kh  = b_mat & 1;

    float c[2][8][4];
    #pragma unroll
    for (int m = 0; m < 2; m++)
        #pragma unroll
        for (int n = 0; n < 8; n++)
            #pragma unroll
            for (int r = 0; r < 4; r++) c[m][n][r] = 0.0f;

    for (int k0 = 0; k0 < DM; k0 += 64) {
        const int kq = k0 >> 3;
        #pragma unroll
        for (int it = 0; it < 4; it++) {
            int f = tid + it * 256;
            int r = f >> 3, ch = f & 7;
            uint32_t off = (uint32_t)(r * 128 + ((ch ^ (r & 7)) << 4));
            size_t gx = (size_t)z * 524288 + (size_t)(m0 + r) * 128 + kq + ch;
            *(uint4*)(smp + XH_OFF + off) = g_Xh4[gx];
            *(uint4*)(smp + XL_OFF + off) = g_Xl4[gx];
            size_t gw = (size_t)z * 131072 + (size_t)(n0 + r) * 128 + kq + ch;
            *(uint4*)(smp + WH_OFF + off) = g_Wh4[gw];
            *(uint4*)(smp + WL_OFF + off) = g_Wl4[gw];
        }
        __syncthreads();

        #pragma unroll
        for (int kc = 0; kc < 4; kc++) {
            uint32_t AH[2][4], AL[2][4];
            #pragma unroll
            for (int m = 0; m < 2; m++) {
                uint32_t ab = (uint32_t)((wm * 32 + m * 16 + a_row) * 128)
                            + (uint32_t)(((2 * kc + a_kh) ^ lx) << 4);
                ldsm_x4(AH[m], sb + XH_OFF + ab);
                ldsm_x4(AL[m], sb + XL_OFF + ab);
            }
            #pragma unroll
            for (int np = 0; np < 4; np++) {
                uint32_t bb = (uint32_t)((wn * 64 + np * 16 + b_nr) * 128)
                            + (uint32_t)(((2 * kc + b_kh) ^ lx) << 4);
                uint32_t BH_[4], BL_[4];
                ldsm_x4(BH_, sb + WH_OFF + bb);
                ldsm_x4(BL_, sb + WL_OFF + bb);
                #pragma unroll
                for (int m = 0; m < 2; m++)
                    #pragma unroll
                    for (int nt = 0; nt < 2; nt++)
                        mma_f16(c[m][2 * np + nt], AH[m], BH_ + 2 * nt);
                #pragma unroll
                for (int m = 0; m < 2; m++)
                    #pragma unroll
                    for (int nt = 0; nt < 2; nt++)
                        mma_f16(c[m][2 * np + nt], AH[m], BL_ + 2 * nt);
                #pragma unroll
                for (int m = 0; m < 2; m++)
                    #pragma unroll
                    for (int nt = 0; nt < 2; nt++)
                        mma_f16(c[m][2 * np + nt], AL[m], BH_ + 2 * nt);
            }
        }
        __syncthreads();
    }

    // ---- epilogue: split Y into attention operands ----
    __half* qh = (__half*)g_Qh4;   __half* ql = (__half*)g_Ql4;
    __half* kh = (__half*)g_Kh4;   __half* kl = (__half*)g_Kl4;
    __half* vth = (__half*)g_VTh4;

    #pragma unroll
    for (int m = 0; m < 2; m++) {
        #pragma unroll
        for (int rr = 0; rr < 2; rr++) {
            int row = m0 + wm * 32 + m * 16 + (lane >> 2) + rr * 8;
            int b   = row >> 11;
            int s   = row & (SEQ - 1);
            #pragma unroll
            for (int n = 0; n < 8; n++) {
                int col = n0 + wn * 64 + n * 8 + (lane & 3) * 2;
                int h   = col >> 6;
                int d   = col & 63;
                int bh  = b * NH + h;
                float e0 = c[m][n][rr * 2 + 0];
                float e1 = c[m][n][rr * 2 + 1];
                if (z == 0) { e0 *= QSCALE; e1 *= QSCALE; }
                if (z != 2) {
                    __half h0, l0, h1, l1;
                    split2(e0, h0, l0);
                    split2(e1, h1, l1);
                    size_t idx = ((size_t)bh * SEQ + s) * HD + d;
                    if (z == 0) {
                        *(__half2*)(qh + idx) = __half2(h0, h1);
                        *(__half2*)(ql + idx) = __half2(l0, l1);
                    } else {
                        *(__half2*)(kh + idx) = __half2(h0, h1);
                        *(__half2*)(kl + idx) = __half2(l0, l1);
                    }
                } else {
                    size_t idx0 = ((size_t)bh * HD + d) * SEQ + s;
                    size_t idx1 = ((size_t)bh * HD + d + 1) * SEQ + s;
                    vth[idx0] = __float2half_rn(e0);
                    vth[idx1] = __float2half_rn(e1);
                }
            }
        }
    }
}

// ---------------------------------------------------------------------------
// FA2-style attention, fp16 mma.sync. CTA = (bh, 128 q-rows).
// 256 threads = 8 warps x 16 q-rows; 2 CTAs/SM = 16 warps/SM.
// cp.async double-buffered K/V staging (stage = Kh+Kl+VTh = 24KB).
// QK: 3 terms; PV: single fp16 term {ph.vh}; normalizer fp32.
// ---------------------------------------------------------------------------
#define QH_OFF   0
#define QL_OFF   16384
#define KV_OFF   32768
#define STAGE_SZ 24576
#define KH_S     0
#define KL_S     8192
#define VTH_S    16384
#define SMEM_DYN 81920

__global__ void __launch_bounds__(256, 2) attn_kernel(float* __restrict__ out)
{
    extern __shared__ char sm[];
    const uint32_t sb = smem_to_u32(sm);
    const int tid = threadIdx.x;
    const int w = tid >> 5, lane = tid & 31;
    const int bh = blockIdx.y;
    const int q0 = blockIdx.x * QT;
    const int mrow0 = w * 16;          // this warp's 16 q-rows

    // ---- load Q (2 splits) into swizzled smem; 2 threads per 128B row ----
    {
        int r = tid >> 1, hf = tid & 1;
        size_t gq = (((size_t)bh * SEQ + q0 + r) * HD) >> 3;
        #pragma unroll
        for (int cc = 0; cc < 4; cc++) {
            int c = hf * 4 + cc;
            uint32_t off = (uint32_t)(r * 128 + ((c ^ (r & 7)) << 4));
            *(uint4*)(sm + QH_OFF + off) = g_Qh4[gq + c];
            *(uint4*)(sm + QL_OFF + off) = g_Ql4[gq + c];
        }
    }

    const int lx    = lane & 7;
    const int a_row = lane & 15;
    const int a_kh  = lane >> 4;
    const int b_mat = lane >> 3;
    const int b_nr  = ((b_mat >> 1) << 3) + (lane & 7);
    const int b_kh  = b_mat & 1;

    const int st_r  = tid >> 2, st_q = tid & 3;   // staging: 4 thr/row, 2 chunks each
    const size_t gk_base = ((size_t)bh * SEQ) * HD >> 3;
    const size_t gv_base = ((size_t)bh * HD * SEQ) >> 3;

    auto stage = [&](int kt, int p) {
        size_t gk = gk_base + ((size_t)kt * KT + st_r) * (HD / 8);
        size_t gv = gv_base + (size_t)st_r * (SEQ / 8) + (size_t)kt * (KT / 8);
        uint32_t base = sb + KV_OFF + p * STAGE_SZ;
        #pragma unroll
        for (int cc = 0; cc < 2; cc++) {
            int c = st_q * 2 + cc;
            uint32_t off = (uint32_t)(st_r * 128 + ((c ^ (st_r & 7)) << 4));
            cp_async16(base + KH_S  + off, g_Kh4  + gk + c);
            cp_async16(base + KL_S  + off, g_Kl4  + gk + c);
            cp_async16(base + VTH_S + off, g_VTh4 + gv + c);
        }
    };

    stage(0, 0);
    CP_COMMIT();
    __syncthreads();   // Q smem visible to all warps

    // cache Qh A-frags across ktiles (16 rows -> one frag per k-chunk)
    uint32_t qhf[4][4];
    #pragma unroll
    for (int kc = 0; kc < 4; kc++) {
        uint32_t addr = sb + QH_OFF + (uint32_t)((mrow0 + a_row) * 128)
                      + (uint32_t)(((2 * kc + a_kh) ^ lx) << 4);
        ldsm_x4(qhf[kc], addr);
    }

    float o[8][4];
    #pragma unroll
    for (int n = 0; n < 8; n++)
        #pragma unroll
        for (int r = 0; r < 4; r++) o[n][r] = 0.0f;

    float mrunA = -1e30f, mrunB = -1e30f;
    float lrunA = 0.0f,   lrunB = 0.0f;

    for (int kt = 0; kt < NKT; kt++) {
        const int p = kt & 1;
        if (kt + 1 < NKT) {
            stage(kt + 1, 1 - p);
            CP_COMMIT();
            CP_WAIT(1);
        } else {
            CP_WAIT(0);
        }
        __syncthreads();

        const uint32_t kvb = sb + KV_OFF + p * STAGE_SZ;

        // ---- S = Q . K^T  (3 fp16 split terms), base-2 logit units ----
        float s[8][4];
        #pragma unroll
        for (int n = 0; n < 8; n++)
            #pragma unroll
            for (int r = 0; r < 4; r++) s[n][r] = 0.0f;

        #pragma unroll
        for (int kc = 0; kc < 4; kc++) {
            uint32_t qlf[4];
            {
                uint32_t ab = (uint32_t)((mrow0 + a_row) * 128)
                            + (uint32_t)(((2 * kc + a_kh) ^ lx) << 4);
                ldsm_x4(qlf, sb + QL_OFF + ab);
            }
            #pragma unroll
            for (int np = 0; np < 4; np++) {
                uint32_t bb = (uint32_t)((np * 16 + b_nr) * 128)
                            + (uint32_t)(((2 * kc + b_kh) ^ lx) << 4);
                uint32_t BH_[4], BL_[4];
                ldsm_x4(BH_, kvb + KH_S + bb);
                ldsm_x4(BL_, kvb + KL_S + bb);
                #pragma unroll
                for (int nt = 0; nt < 2; nt++)
                    mma_f16(s[2 * np + nt], qhf[kc], BH_ + 2 * nt);
                #pragma unroll
                for (int nt = 0; nt < 2; nt++)
                    mma_f16(s[2 * np + nt], qhf[kc], BL_ + 2 * nt);
                #pragma unroll
                for (int nt = 0; nt < 2; nt++)
                    mma_f16(s[2 * np + nt], qlf, BH_ + 2 * nt);
            }
        }

        // ---- online softmax (base-2, MUFU ex2) ----
        {
            float mxA = -1e30f, mxB = -1e30f;
            #pragma unroll
            for (int n = 0; n < 8; n++) {
                mxA = fmaxf(mxA, fmaxf(s[n][0], s[n][1]));
                mxB = fmaxf(mxB, fmaxf(s[n][2], s[n][3]));
            }
            mxA = fmaxf(mxA, __shfl_xor_sync(0xffffffffu, mxA, 1));
            mxA = fmaxf(mxA, __shfl_xor_sync(0xffffffffu, mxA, 2));
            mxB = fmaxf(mxB, __shfl_xor_sync(0xffffffffu, mxB, 1));
            mxB = fmaxf(mxB, __shfl_xor_sync(0xffffffffu, mxB, 2));
            float mnA = fmaxf(mrunA, mxA);
            float mnB = fmaxf(mrunB, mxB);
            float cA = ex2f(mrunA - mnA);
            float cB = ex2f(mrunB - mnB);
            float sA = 0.0f, sB = 0.0f;
            #pragma unroll
            for (int n = 0; n < 8; n++) {
                s[n][0] = ex2f(s[n][0] - mnA); sA += s[n][0];
                s[n][1] = ex2f(s[n][1] - mnA); sA += s[n][1];
                s[n][2] = ex2f(s[n][2] - mnB); sB += s[n][2];
                s[n][3] = ex2f(s[n][3] - mnB); sB += s[n][3];
            }
            sA += __shfl_xor_sync(0xffffffffu, sA, 1);
            sA += __shfl_xor_sync(0xffffffffu, sA, 2);
            sB += __shfl_xor_sync(0xffffffffu, sB, 1);
            sB += __shfl_xor_sync(0xffffffffu, sB, 2);
            lrunA = lrunA * cA + sA;
            lrunB = lrunB * cB + sB;
            mrunA = mnA;  mrunB = mnB;
            #pragma unroll
            for (int n = 0; n < 8; n++) {
                o[n][0] *= cA; o[n][1] *= cA;
                o[n][2] *= cB; o[n][3] *= cB;
            }
        }

        // ---- fused P-pack + PV per k-chunk (single fp16 term) ----
        #pragma unroll
        for (int kc = 0; kc < 4; kc++) {
            uint32_t ph[4];
            #pragma unroll
            for (int r = 0; r < 4; r++) {
                int nsrc = 2 * kc + (r >> 1);
                int base = (r & 1) * 2;
                __half2 hv = __floats2half2_rn(s[nsrc][base + 0], s[nsrc][base + 1]);
                ph[r] = *(uint32_t*)&hv;
            }
            #pragma unroll
            for (int np = 0; np < 4; np++) {
                uint32_t bb = (uint32_t)((np * 16 + b_nr) * 128)
                            + (uint32_t)(((2 * kc + b_kh) ^ lx) << 4);
                uint32_t BH_[4];
                ldsm_x4(BH_, kvb + VTH_S + bb);
                #pragma unroll
                for (int nt = 0; nt < 2; nt++)
                    mma_f16(o[2 * np + nt], ph, BH_ + 2 * nt);
            }
        }
        __syncthreads();   // all warps done reading buffer p before overwrite
    }

    // ---- epilogue: normalize, write fp32 [b, s, h*64 + d] ----
    const int b = bh >> 4, h = bh & (NH - 1);
    {
        float invA = 1.0f / lrunA;
        float invB = 1.0f / lrunB;
        int rA = q0 + mrow0 + (lane >> 2);
        int rB = rA + 8;
        #pragma unroll
        for (int n = 0; n < 8; n++) {
            int col = h * HD + n * 8 + (lane & 3) * 2;
            float2 vA = make_float2(o[n][0] * invA, o[n][1] * invA);
            float2 vB = make_float2(o[n][2] * invB, o[n][3] * invB);
            *(float2*)(out + ((size_t)b * SEQ + rA) * DM + col) = vA;
            *(float2*)(out + ((size_t)b * SEQ + rB) * DM + col) = vB;
        }
    }
}

extern "C" void kernel_launch(void* const* d_in, const int* in_sizes, int n_in,
                              void* d_out, int out_size)
{
    const float* q  = (const float*)d_in[0];
    const float* k  = (const float*)d_in[1];
    const float* v  = (const float*)d_in[2];
    const float* Wq = (const float*)d_in[3];
    const float* Wk = (const float*)d_in[4];
    const float* Wv = (const float*)d_in[5];
    float* out = (float*)d_out;

    cudaFuncSetAttribute(proj_mma_kernel, cudaFuncAttributeMaxDynamicSharedMemorySize, SMEM_PROJ);
    cudaFuncSetAttribute(attn_kernel, cudaFuncAttributeMaxDynamicSharedMemorySize, SMEM_DYN);

    prep_kernel<<<2048, 256>>>(q, k, v, Wq, Wk, Wv);

    dim3 pgrid(DM / 128, (BS * SEQ) / 128, 3);
    proj_mma_kernel<<<pgrid, 256, SMEM_PROJ>>>();

    dim3 agrid(SEQ / QT, BH);
    attn_kernel<<<agrid, 256, SMEM_DYN>>>(out);
}